// round 9
// baseline (speedup 1.0000x reference)
#include <cuda_runtime.h>

#define NP  66
#define NPP 72

// ---------------- scratch (no allocations allowed) ----------------
__device__ __align__(16) float g_O0[8 * NP * 32 * 32];
__device__ __align__(16) float g_O1[8 * NP * 64 * 64];
__device__ __align__(16) float g_O2[8 * NP * 128 * 128];

// stage-3 weights/bias in constant memory (filled by cudaMemcpyToSymbolAsync)
__constant__ float4 c_W3[72 * 16];   // [pair][k/4], float4 view of [66][64] row-major
__constant__ float  c_B3[72];

// Precomputed OvO vote masks over the 66 pairs (+6 pad bits always 0).
// c_MA[k] = {Imask word0, word1, word2, Jmask word0}
// c_MB[k] = {Jmask word1, word2, 0, 0}
__constant__ int4 c_MA[12] = {
  {0x000007FF, 0x00000000, 0x0, 0x00000000},
  {0x001FF800, 0x00000000, 0x0, 0x00000001},
  {0x3FE00000, 0x00000000, 0x0, 0x00000802},
  {(int)0xC0000000, 0x0000003F, 0x0, 0x00201004},
  {0x00000000, 0x00001FC0, 0x0, 0x40402008},
  {0x00000000, 0x0007E000, 0x0, (int)0x80804010},
  {0x00000000, 0x00F80000, 0x0, 0x01008020},
  {0x00000000, 0x0F000000, 0x0, 0x02010040},
  {0x00000000, 0x70000000, 0x0, 0x04020080},
  {0x00000000, (int)0x80000000, 0x1, 0x08040100},
  {0x00000000, 0x00000000, 0x2, 0x10080200},
  {0x00000000, 0x00000000, 0x0, 0x20100400}};
__constant__ int4 c_MB[12] = {
  {0x00000000, 0x0, 0, 0}, {0x00000000, 0x0, 0, 0},
  {0x00000000, 0x0, 0, 0}, {0x00000000, 0x0, 0, 0},
  {0x00000000, 0x0, 0, 0}, {0x00000040, 0x0, 0, 0},
  {0x00002081, 0x0, 0, 0}, {0x00084102, 0x0, 0, 0},
  {0x01108204, 0x0, 0, 0}, {0x12210408, 0x0, 0, 0},
  {(int)0xA4420810, 0x0, 0, 0}, {0x48841020, 0x3, 0, 0}};

// ---------------- helpers ----------------
__device__ __forceinline__ void ffma2(unsigned long long& d,
                                      unsigned long long a,
                                      unsigned long long b) {
  asm("fma.rn.f32x2 %0, %1, %2, %0;" : "+l"(d) : "l"(a), "l"(b));
}
__device__ __forceinline__ unsigned long long pack2(float x) {
  unsigned long long r;
  asm("mov.b64 %0, {%1, %1};" : "=l"(r) : "f"(x));
  return r;
}
__device__ __forceinline__ float2 unpack2(unsigned long long u) {
  float2 r;
  asm("mov.b64 {%0, %1}, %2;" : "=f"(r.x), "=f"(r.y) : "l"(u));
  return r;
}
__device__ __forceinline__ unsigned su32(const void* p) {
  return (unsigned)__cvta_generic_to_shared(p);
}
__device__ __forceinline__ void cpa16(unsigned dst, const void* src) {
  asm volatile("cp.async.cg.shared.global [%0], [%1], 16;" :: "r"(dst), "l"(src));
}
__device__ __forceinline__ void cpa4(unsigned dst, const void* src) {
  asm volatile("cp.async.ca.shared.global [%0], [%1], 4;" :: "r"(dst), "l"(src));
}
#define CPA_COMMIT() asm volatile("cp.async.commit_group;" ::: "memory")
#define CPA_WAIT(n)  asm volatile("cp.async.wait_group %0;" :: "n"(n) : "memory")

#define XBUF (8 * 128)
#define WBUF (8 * NPP)

// ======================= conv_all (unchanged from R8) ========================
#define COMPUTE8C(Wb, Xb)                                                      \
  _Pragma("unroll")                                                            \
  for (int k = 0; k < 8; k++) {                                                \
    const float4 wA = *(const float4*)&(Wb)[k * NPP + 8 * wrp];                \
    const float4 wB = *(const float4*)&(Wb)[k * NPP + 8 * wrp + 4];            \
    const ulonglong2 xv = *(const ulonglong2*)&(Xb)[k * 128 + 4 * ln];         \
    unsigned long long w_[8] = {pack2(wA.x), pack2(wA.y), pack2(wA.z),         \
                                pack2(wA.w), pack2(wB.x), pack2(wB.y),         \
                                pack2(wB.z), pack2(wB.w)};                     \
    _Pragma("unroll")                                                          \
    for (int a = 0; a < 8; a++) {                                              \
      ffma2(acc[a][0], w_[a], xv.x);                                           \
      ffma2(acc[a][1], w_[a], xv.y);                                           \
    }                                                                          \
  }

#define ISSUE_CHUNK_C(j, XSTRIDE)                                              \
  do {                                                                         \
    int _b = (j) & 3, _c0 = (j) * 8;                                           \
    if (hasx) cpa16(xd0 + _b * (XBUF * 4), xsrc + (size_t)_c0 * (XSTRIDE));    \
    cpa4(wda0 + _b * (WBUF * 4), wsa + _c0);                                   \
    if (hasb) cpa4(wdb0 + _b * (WBUF * 4), wsb + _c0);                         \
  } while (0)

template <int C, int SS>
__device__ __forceinline__ void conv_body(const float* __restrict__ X,
                                          const float* __restrict__ W,
                                          const float* __restrict__ bias,
                                          float* __restrict__ Og,
                                          int n, int px0,
                                          float* Ws, float* Xs) {
  const int tid = threadIdx.x;
  const int wrp = tid >> 5, ln = tid & 31;

  unsigned long long acc[8][2];
#pragma unroll
  for (int a = 0; a < 8; a++) {
    int p = 8 * wrp + a;
    unsigned long long pk = pack2((p < NP) ? bias[p] : 0.0f);
    acc[a][0] = pk; acc[a][1] = pk;
  }

  const bool hasx = tid < 256;
  const int ch_ = tid >> 5, t_ = tid & 31;
  const unsigned xd0 = su32(&Xs[ch_ * 128 + 4 * t_]);
  const float* xsrc = X + (size_t)n * C * SS + px0 + (size_t)ch_ * SS + 4 * t_;

  const int ka = tid / 66, pa = tid - 66 * ka;
  const int sb_ = tid + 288;
  const bool hasb = sb_ < 528;
  const int kb = sb_ / 66, pb = sb_ - 66 * kb;
  const unsigned wda0 = su32(&Ws[ka * NPP + pa]);
  const unsigned wdb0 = su32(&Ws[kb * NPP + pb]);
  const float* wsa = W + pa * C + ka;
  const float* wsb = W + pb * C + kb;

  if (tid < 192) {
    int b = tid / 48, r = tid - 48 * b;
    int k = r / 6, p = 66 + (r - 6 * k);
    Ws[b * WBUF + k * NPP + p] = 0.0f;
  }

  ISSUE_CHUNK_C(0, SS); CPA_COMMIT();
  ISSUE_CHUNK_C(1, SS); CPA_COMMIT();
  ISSUE_CHUNK_C(2, SS); CPA_COMMIT();

  const int NIT = C / 8;
  for (int i = 0; i < NIT; i++) {
    CPA_WAIT(2);
    __syncthreads();
    {
      const float* Wb = Ws + (i & 3) * WBUF;
      const float* Xb = Xs + (i & 3) * XBUF;
      COMPUTE8C(Wb, Xb);
    }
    if (i + 3 < NIT) ISSUE_CHUNK_C(i + 3, SS);
    CPA_COMMIT();
  }

  float* On = Og + (size_t)n * NP * SS + px0 + 4 * ln;
#pragma unroll
  for (int a = 0; a < 8; a++) {
    int p = 8 * wrp + a;
    if (p < NP) {
      ulonglong2 v;
      v.x = acc[a][0]; v.y = acc[a][1];
      *(ulonglong2*)&On[(size_t)p * SS] = v;
    }
  }
}

__global__ __launch_bounds__(288, 3) void conv_all(
    const float* __restrict__ s0, const float* __restrict__ s1,
    const float* __restrict__ s2, const float* __restrict__ w0,
    const float* __restrict__ w1, const float* __restrict__ w2,
    const float* __restrict__ b0, const float* __restrict__ b1,
    const float* __restrict__ b2) {
  __shared__ __align__(16) float Ws[4 * WBUF];
  __shared__ __align__(16) float Xs[4 * XBUF];
  int bid = blockIdx.x;
  if (bid < 64) {
    conv_body<512, 32 * 32>(s0, w0, b0, g_O0, bid >> 3, (bid & 7) << 7, Ws, Xs);
  } else if (bid < 320) {
    int q = bid - 64;
    conv_body<256, 64 * 64>(s1, w1, b1, g_O1, q >> 5, (q & 31) << 7, Ws, Xs);
  } else {
    int q = bid - 320;
    conv_body<128, 128 * 128>(s2, w2, b2, g_O2, q >> 7, (q & 127) << 7, Ws, Xs);
  }
}

// ======================= fused kernel =======================================
// tile = 8 rows x 16 cols; warp = 8 pairs, lane = 4-px quad (row=ln>>2, qc=ln&3)
// Weights/bias from constant memory (no L1 traffic, no W ring).
#define COMPUTE8F(Xb, ic)                                                      \
  do {                                                                         \
    ulonglong2 xr[8];                                                          \
    _Pragma("unroll")                                                          \
    for (int k = 0; k < 8; k++)                                                \
      xr[k] = *(const ulonglong2*)&(Xb)[k * 128 + 4 * ln];                     \
    _Pragma("unroll")                                                          \
    for (int a = 0; a < 8; a++) {                                              \
      const int pw = (8 * wrp + a) * 16 + (ic) * 2;                            \
      const float4 wq0 = c_W3[pw];                                             \
      const float4 wq1 = c_W3[pw + 1];                                         \
      unsigned long long w_[8] = {pack2(wq0.x), pack2(wq0.y), pack2(wq0.z),    \
                                  pack2(wq0.w), pack2(wq1.x), pack2(wq1.y),    \
                                  pack2(wq1.z), pack2(wq1.w)};                 \
      _Pragma("unroll")                                                        \
      for (int k = 0; k < 8; k++) {                                            \
        ffma2(acc[a][0], w_[k], xr[k].x);                                      \
        ffma2(acc[a][1], w_[k], xr[k].y);                                      \
      }                                                                        \
    }                                                                          \
  } while (0)

__global__ __launch_bounds__(288, 2) void fused_kernel(
    const float* __restrict__ X, float* __restrict__ out) {
  __shared__ __align__(16) float Xs[4 * XBUF];   // reused for sign bytes later
  __shared__ __align__(16) float sO2[NP * 84];   // 6 rows x 14 (base col 8tx-5)
  __shared__ __align__(16) float sO1[NP * 40];   // 4 rows x 5 dup-pair slots
  __shared__ __align__(16) float sO0[NP * 18];   // 3 rows x 3 dup-pair slots

  const int tid = threadIdx.x;
  const int wrp = tid >> 5, ln = tid & 31;
  const int n = blockIdx.y;
  const int ty = blockIdx.x >> 4, tx = blockIdx.x & 15;
  const int y0 = ty << 3, x0 = tx << 4;

  // ---- mainloop slot addressing (X only) ----
  const bool hasx = tid < 256;
  const int ch_ = tid >> 5, t_ = tid & 31;
  const unsigned xd0 = su32(&Xs[ch_ * 128 + 4 * t_]);
  const float* Xn = X + (size_t)n * 64 * 65536;
  const float* xsrc = Xn + (size_t)ch_ * 65536 + (y0 + (t_ >> 2)) * 256 + x0 + ((t_ & 3) << 2);

#define ISSUE_CHUNK_F(j)                                                       \
  do {                                                                         \
    int _b = (j) & 3;                                                          \
    if (hasx) cpa16(xd0 + _b * (XBUF * 4), xsrc + (size_t)((j) * 8) * 65536);  \
  } while (0)

  ISSUE_CHUNK_F(0); CPA_COMMIT();
  ISSUE_CHUNK_F(1); CPA_COMMIT();
  ISSUE_CHUNK_F(2); CPA_COMMIT();

  // ---- sO staging (group 3): clamped cpa4 into parity-engineered layouts ----
  {
    const int by2 = (y0 >> 1) - 1, a2 = 8 * tx - 5;
    const float* src = g_O2 + (size_t)n * NP * 16384;
    for (int i = tid; i < NP * 84; i += 288) {
      int p = i / 84, r = i - p * 84;
      int rr = r / 14, cc = r - rr * 14;
      int sy = min(max(by2 + rr, 0), 127);
      int sx = min(max(a2 + cc, 0), 127);
      cpa4(su32(&sO2[i]), src + p * 16384 + sy * 128 + sx);
    }
  }
  {
    const int by1 = (y0 >> 2) - 1, a1 = 4 * tx - 1;
    const float* src = g_O1 + (size_t)n * NP * 4096;
    for (int i = tid; i < NP * 40; i += 288) {
      int p = i / 40, r = i - p * 40;
      int rr = r / 10, s = r - rr * 10;
      int col = a1 + (s >> 1) + (s & 1);
      int sy = min(max(by1 + rr, 0), 63);
      int sx = min(max(col, 0), 63);
      cpa4(su32(&sO1[i]), src + p * 4096 + sy * 64 + sx);
    }
  }
  {
    const int by0 = (y0 >> 3) - 1, a0 = 2 * tx - 1;
    const float* src = g_O0 + (size_t)n * NP * 1024;
    for (int i = tid; i < NP * 18; i += 288) {
      int p = i / 18, r = i - p * 18;
      int rr = r / 6, s = r - rr * 6;
      int col = a0 + (s >> 1) + (s & 1);
      int sy = min(max(by0 + rr, 0), 31);
      int sx = min(max(col, 0), 31);
      cpa4(su32(&sO0[i]), src + p * 1024 + sy * 32 + sx);
    }
  }
  CPA_COMMIT();   // group 3 = staging (drained by iter 2 << epilogue)

  // ---- stage3 GEMM mainloop (C=64), 4-deep cp.async ring, const weights ----
  unsigned long long acc[8][2];
#pragma unroll
  for (int a = 0; a < 8; a++) {
    int p = 8 * wrp + a;
    unsigned long long pk = pack2((p < NP) ? c_B3[p] : 0.0f);
    acc[a][0] = pk; acc[a][1] = pk;
  }

  for (int i = 0; i < 8; i++) {
    CPA_WAIT(2);
    __syncthreads();
    {
      const float* Xb = Xs + (i & 3) * XBUF;
      COMPUTE8F(Xb, i);
    }
    if (i + 3 < 8) ISSUE_CHUNK_F(i + 3);
    CPA_COMMIT();
  }
  __syncthreads();

  // ---- epilogue: separable bilinear, all taps via aligned LDS.64 ----
  {
    const int r = ln >> 2, qc = ln & 3;
    const float WY2[8] = {.75f, .25f, .75f, .25f, .75f, .25f, .75f, .25f};
    const int   RY2[8] = {0, 1, 1, 2, 2, 3, 3, 4};
    const float WY1[8] = {.625f, .875f, .125f, .375f, .625f, .875f, .125f, .375f};
    const int   RY1[8] = {0, 0, 1, 1, 1, 1, 2, 2};
    const float WY0[8] = {.5625f, .6875f, .8125f, .9375f, .0625f, .1875f, .3125f, .4375f};
    const int   RY0[8] = {0, 0, 0, 0, 1, 1, 1, 1};
    const int ry2 = RY2[r]; const float wy2 = WY2[r];
    const int ry1 = RY1[r]; const float wy1 = WY1[r];
    const int ry0 = RY0[r]; const float wy0 = WY0[r];
    const int w0qc = (qc + 1) >> 1;       // {0,1,1,2}
    const float fx0adj = (qc & 1) ? 0.5f : 0.0f;

    const int   LX2[4] = {0, 1, 1, 2};
    const float FX2[4] = {.75f, .25f, .75f, .25f};
    const int   LX1[4] = {0, 0, 1, 1};
    const float FX1[4] = {.625f, .875f, .125f, .375f};
    const float FX0[4] = {.5625f, .6875f, .8125f, .9375f};

    const int o2 = ry2 * 14 + 2 * qc + 4;
    const int o1 = ry1 * 10 + 2 * qc;
    const int o0 = ry0 * 6 + 2 * w0qc;

    unsigned by[4] = {0, 0, 0, 0};
#pragma unroll
    for (int a = 0; a < 8; a++) {
      int p = 8 * wrp + a;
      float v[4];
      float2 u0 = unpack2(acc[a][0]), u1 = unpack2(acc[a][1]);
      v[0] = u0.x; v[1] = u0.y; v[2] = u1.x; v[3] = u1.y;
      if (p < NP) {
        // L2: 4 y-lerped taps via 4x LDS.64
        const float* A2 = &sO2[p * 84 + o2];
        float2 a01 = *(const float2*)A2;
        float2 a23 = *(const float2*)(A2 + 2);
        float2 b01 = *(const float2*)(A2 + 14);
        float2 b23 = *(const float2*)(A2 + 16);
        float t2[4] = {a01.x + wy2 * (b01.x - a01.x),
                       a01.y + wy2 * (b01.y - a01.y),
                       a23.x + wy2 * (b23.x - a23.x),
                       a23.y + wy2 * (b23.y - a23.y)};
        // L1: 3 y-lerped taps via 4x LDS.64 (dup-pair slots)
        const float* A1 = &sO1[p * 40 + o1];
        float2 c01 = *(const float2*)A1;
        float2 c12 = *(const float2*)(A1 + 2);
        float2 d01 = *(const float2*)(A1 + 10);
        float2 d12 = *(const float2*)(A1 + 12);
        float t1[3] = {c01.x + wy1 * (d01.x - c01.x),
                       c01.y + wy1 * (d01.y - c01.y),
                       c12.y + wy1 * (d12.y - c12.y)};
        // L0: 2 y-lerped taps via 2x LDS.64
        const float* A0 = &sO0[p * 18 + o0];
        float2 e01 = *(const float2*)A0;
        float2 f01 = *(const float2*)(A0 + 6);
        float t0a = e01.x + wy0 * (f01.x - e01.x);
        float t0b = e01.y + wy0 * (f01.y - e01.y);
#pragma unroll
        for (int q = 0; q < 4; q++) {
          v[q] += t2[LX2[q]] + FX2[q] * (t2[LX2[q] + 1] - t2[LX2[q]]);
          v[q] += t1[LX1[q]] + FX1[q] * (t1[LX1[q] + 1] - t1[LX1[q]]);
          float f0 = FX0[q] - fx0adj;
          v[q] += t0a + f0 * (t0b - t0a);
        }
      }
#pragma unroll
      for (int q = 0; q < 4; q++) by[q] |= ((v[q] > 0.0f) ? 1u : 0u) << a;
    }
    unsigned* sS32 = (unsigned*)Xs;
    sS32[wrp * 32 + ln] = by[0] | (by[1] << 8) | (by[2] << 16) | (by[3] << 24);
  }
  __syncthreads();

  // ---- vote via popcount against constant masks, coalesced store ----
  if (tid < 128) {
    const unsigned char* sb8 = (const unsigned char*)Xs;
    unsigned b0 = sb8[tid],           b1 = sb8[128 + tid];
    unsigned b2 = sb8[256 + tid],     b3 = sb8[384 + tid];
    unsigned b4 = sb8[512 + tid],     b5 = sb8[640 + tid];
    unsigned b6 = sb8[768 + tid],     b7 = sb8[896 + tid];
    unsigned b8 = sb8[1024 + tid];
    unsigned sw0 = b0 | (b1 << 8) | (b2 << 16) | (b3 << 24);
    unsigned sw1 = b4 | (b5 << 8) | (b6 << 16) | (b7 << 24);
    unsigned sw2 = b8;
    int row = tid >> 4, col = tid & 15;
    float* op = out + (size_t)n * 12 * 65536 + (y0 + row) * 256 + (x0 + col);
#pragma unroll
    for (int k = 0; k < 12; k++) {
      int4 A = c_MA[k];
      int4 B = c_MB[k];
      int cnt = __popc(sw0 & (unsigned)A.x) + __popc(sw1 & (unsigned)A.y) +
                __popc(sw2 & (unsigned)A.z) - __popc(sw0 & (unsigned)A.w) -
                __popc(sw1 & (unsigned)B.x) - __popc(sw2 & (unsigned)B.y) + k;
      op[(size_t)k << 16] = (float)cnt;
    }
  }
}

// ---------------- launcher ----------------
extern "C" void kernel_launch(void* const* d_in, const int* in_sizes, int n_in,
                              void* d_out, int out_size) {
  const float* st[4] = {0, 0, 0, 0};
  const float* w[4] = {0, 0, 0, 0};
  const float* bb[4] = {0, 0, 0, 0};
  int bc = 0;
  for (int i = 0; i < n_in; i++) {
    switch (in_sizes[i]) {
      case 4194304:  st[0] = (const float*)d_in[i]; break;  // 8*512*32*32
      case 8388608:  st[1] = (const float*)d_in[i]; break;  // 8*256*64*64
      case 16777216: st[2] = (const float*)d_in[i]; break;  // 8*128*128*128
      case 33554432: st[3] = (const float*)d_in[i]; break;  // 8*64*256*256
      case 33792: w[0] = (const float*)d_in[i]; break;      // 66*512
      case 16896: w[1] = (const float*)d_in[i]; break;      // 66*256
      case 8448:  w[2] = (const float*)d_in[i]; break;      // 66*128
      case 4224:  w[3] = (const float*)d_in[i]; break;      // 66*64
      case 66:
        if (bc < 4) bb[bc++] = (const float*)d_in[i];       // b0..b3 in order
        break;
      default: break;  // last_only (==1 always per setup_inputs)
    }
  }

  // stage-3 weights/bias -> constant memory (d2d memcpy nodes, graph-legal)
  cudaMemcpyToSymbolAsync(c_W3, w[3], 66 * 64 * sizeof(float), 0,
                          cudaMemcpyDeviceToDevice, 0);
  cudaMemcpyToSymbolAsync(c_B3, bb[3], 66 * sizeof(float), 0,
                          cudaMemcpyDeviceToDevice, 0);

  conv_all<<<1344, 288>>>(st[0], st[1], st[2], w[0], w[1], w[2],
                          bb[0], bb[1], bb[2]);
  fused_kernel<<<dim3(512, 8), 288>>>(st[3], (float*)d_out);
}

// round 10
// speedup vs baseline: 3.3881x; 3.3881x over previous
#include <cuda_runtime.h>

#define NP  66
#define NPP 72

// ---------------- scratch (no allocations allowed) ----------------
__device__ __align__(16) float g_O0[8 * NP * 32 * 32];
__device__ __align__(16) float g_O1[8 * NP * 64 * 64];
__device__ __align__(16) float g_O2[8 * NP * 128 * 128];

// Precomputed OvO vote masks over the 66 pairs (+6 pad bits always 0).
// c_MA[k] = {Imask word0, word1, word2, Jmask word0}
// c_MB[k] = {Jmask word1, word2, 0, 0}
__constant__ int4 c_MA[12] = {
  {0x000007FF, 0x00000000, 0x0, 0x00000000},
  {0x001FF800, 0x00000000, 0x0, 0x00000001},
  {0x3FE00000, 0x00000000, 0x0, 0x00000802},
  {(int)0xC0000000, 0x0000003F, 0x0, 0x00201004},
  {0x00000000, 0x00001FC0, 0x0, 0x40402008},
  {0x00000000, 0x0007E000, 0x0, (int)0x80804010},
  {0x00000000, 0x00F80000, 0x0, 0x01008020},
  {0x00000000, 0x0F000000, 0x0, 0x02010040},
  {0x00000000, 0x70000000, 0x0, 0x04020080},
  {0x00000000, (int)0x80000000, 0x1, 0x08040100},
  {0x00000000, 0x00000000, 0x2, 0x10080200},
  {0x00000000, 0x00000000, 0x0, 0x20100400}};
__constant__ int4 c_MB[12] = {
  {0x00000000, 0x0, 0, 0}, {0x00000000, 0x0, 0, 0},
  {0x00000000, 0x0, 0, 0}, {0x00000000, 0x0, 0, 0},
  {0x00000000, 0x0, 0, 0}, {0x00000040, 0x0, 0, 0},
  {0x00002081, 0x0, 0, 0}, {0x00084102, 0x0, 0, 0},
  {0x01108204, 0x0, 0, 0}, {0x12210408, 0x0, 0, 0},
  {(int)0xA4420810, 0x0, 0, 0}, {0x48841020, 0x3, 0, 0}};

// ---------------- helpers ----------------
__device__ __forceinline__ void ffma2(unsigned long long& d,
                                      unsigned long long a,
                                      unsigned long long b) {
  asm("fma.rn.f32x2 %0, %1, %2, %0;" : "+l"(d) : "l"(a), "l"(b));
}
__device__ __forceinline__ unsigned long long pack2(float x) {
  unsigned long long r;
  asm("mov.b64 %0, {%1, %1};" : "=l"(r) : "f"(x));
  return r;
}
__device__ __forceinline__ float2 unpack2(unsigned long long u) {
  float2 r;
  asm("mov.b64 {%0, %1}, %2;" : "=f"(r.x), "=f"(r.y) : "l"(u));
  return r;
}
__device__ __forceinline__ unsigned su32(const void* p) {
  return (unsigned)__cvta_generic_to_shared(p);
}
__device__ __forceinline__ void cpa16(unsigned dst, const void* src) {
  asm volatile("cp.async.cg.shared.global [%0], [%1], 16;" :: "r"(dst), "l"(src));
}
__device__ __forceinline__ void cpa4(unsigned dst, const void* src) {
  asm volatile("cp.async.ca.shared.global [%0], [%1], 4;" :: "r"(dst), "l"(src));
}
#define CPA_COMMIT() asm volatile("cp.async.commit_group;" ::: "memory")
#define CPA_WAIT(n)  asm volatile("cp.async.wait_group %0;" :: "n"(n) : "memory")

#define XBUF (8 * 128)
#define WBUF (8 * NPP)

// compute one 8-channel chunk: warp 'wrp' owns pairs 8wrp..8wrp+7,
// lane 'ln' owns pixels 4ln..4ln+3
#define COMPUTE8(Wb, Xb)                                                       \
  _Pragma("unroll")                                                            \
  for (int k = 0; k < 8; k++) {                                                \
    const float4 wA = *(const float4*)&(Wb)[k * NPP + 8 * wrp];                \
    const float4 wB = *(const float4*)&(Wb)[k * NPP + 8 * wrp + 4];            \
    const ulonglong2 xv = *(const ulonglong2*)&(Xb)[k * 128 + 4 * ln];         \
    unsigned long long w_[8] = {pack2(wA.x), pack2(wA.y), pack2(wA.z),         \
                                pack2(wA.w), pack2(wB.x), pack2(wB.y),         \
                                pack2(wB.z), pack2(wB.w)};                     \
    _Pragma("unroll")                                                          \
    for (int a = 0; a < 8; a++) {                                              \
      ffma2(acc[a][0], w_[a], xv.x);                                           \
      ffma2(acc[a][1], w_[a], xv.y);                                           \
    }                                                                          \
  }

// issue loads of channel-chunk j into ring buffer j&3
#define ISSUE_CHUNK(j, XSTRIDE)                                                \
  do {                                                                         \
    int _b = (j) & 3, _c0 = (j) * 8;                                           \
    if (hasx) cpa16(xd0 + _b * (XBUF * 4), xsrc + (size_t)_c0 * (XSTRIDE));    \
    cpa4(wda0 + _b * (WBUF * 4), wsa + _c0);                                   \
    if (hasb) cpa4(wdb0 + _b * (WBUF * 4), wsb + _c0);                         \
  } while (0)

// ---------------- conv body: 66 pairs x 128 px, 4-deep cp.async ring ---------
template <int C, int SS>
__device__ __forceinline__ void conv_body(const float* __restrict__ X,
                                          const float* __restrict__ W,
                                          const float* __restrict__ bias,
                                          float* __restrict__ Og,
                                          int n, int px0,
                                          float* Ws, float* Xs) {
  const int tid = threadIdx.x;
  const int wrp = tid >> 5, ln = tid & 31;

  unsigned long long acc[8][2];
#pragma unroll
  for (int a = 0; a < 8; a++) {
    int p = 8 * wrp + a;
    unsigned long long pk = pack2((p < NP) ? bias[p] : 0.0f);
    acc[a][0] = pk; acc[a][1] = pk;
  }

  const bool hasx = tid < 256;
  const int ch_ = tid >> 5, t_ = tid & 31;
  const unsigned xd0 = su32(&Xs[ch_ * 128 + 4 * t_]);
  const float* xsrc = X + (size_t)n * C * SS + px0 + (size_t)ch_ * SS + 4 * t_;

  const int ka = tid / 66, pa = tid - 66 * ka;
  const int sb_ = tid + 288;
  const bool hasb = sb_ < 528;
  const int kb = sb_ / 66, pb = sb_ - 66 * kb;
  const unsigned wda0 = su32(&Ws[ka * NPP + pa]);
  const unsigned wdb0 = su32(&Ws[kb * NPP + pb]);
  const float* wsa = W + pa * C + ka;
  const float* wsb = W + pb * C + kb;

  if (tid < 192) {
    int b = tid / 48, r = tid - 48 * b;
    int k = r / 6, p = 66 + (r - 6 * k);
    Ws[b * WBUF + k * NPP + p] = 0.0f;
  }

  ISSUE_CHUNK(0, SS); CPA_COMMIT();
  ISSUE_CHUNK(1, SS); CPA_COMMIT();
  ISSUE_CHUNK(2, SS); CPA_COMMIT();

  const int NIT = C / 8;
  for (int i = 0; i < NIT; i++) {
    CPA_WAIT(2);
    __syncthreads();
    {
      const float* Wb = Ws + (i & 3) * WBUF;
      const float* Xb = Xs + (i & 3) * XBUF;
      COMPUTE8(Wb, Xb);
    }
    if (i + 3 < NIT) ISSUE_CHUNK(i + 3, SS);
    CPA_COMMIT();
  }

  float* On = Og + (size_t)n * NP * SS + px0 + 4 * ln;
#pragma unroll
  for (int a = 0; a < 8; a++) {
    int p = 8 * wrp + a;
    if (p < NP) {
      ulonglong2 v;
      v.x = acc[a][0]; v.y = acc[a][1];
      *(ulonglong2*)&On[(size_t)p * SS] = v;
    }
  }
}

// ---------------- merged conv for stages 0..2 ----------------
__global__ __launch_bounds__(288, 3) void conv_all(
    const float* __restrict__ s0, const float* __restrict__ s1,
    const float* __restrict__ s2, const float* __restrict__ w0,
    const float* __restrict__ w1, const float* __restrict__ w2,
    const float* __restrict__ b0, const float* __restrict__ b1,
    const float* __restrict__ b2) {
  __shared__ __align__(16) float Ws[4 * WBUF];
  __shared__ __align__(16) float Xs[4 * XBUF];
  int bid = blockIdx.x;
  if (bid < 64) {
    conv_body<512, 32 * 32>(s0, w0, b0, g_O0, bid >> 3, (bid & 7) << 7, Ws, Xs);
  } else if (bid < 320) {
    int q = bid - 64;
    conv_body<256, 64 * 64>(s1, w1, b1, g_O1, q >> 5, (q & 31) << 7, Ws, Xs);
  } else {
    int q = bid - 320;
    conv_body<128, 128 * 128>(s2, w2, b2, g_O2, q >> 7, (q & 127) << 7, Ws, Xs);
  }
}

// ---------------- fused: stage3 conv + bilinear pyramid sum + popc vote ------
// tile = 8 rows x 16 cols; warp = 8 pairs, lane = 4-px quad (row=ln>>2, qc=ln&3)
__global__ __launch_bounds__(288, 2) void fused_kernel(
    const float* __restrict__ X, const float* __restrict__ W,
    const float* __restrict__ bias, float* __restrict__ out) {
  __shared__ __align__(16) float Ws[4 * WBUF];
  __shared__ __align__(16) float Xs[4 * XBUF];   // reused for sign bytes later
  __shared__ __align__(16) float sO2[NP * 84];   // 6 rows x 14 (base col 8tx-5)
  __shared__ __align__(16) float sO1[NP * 40];   // 4 rows x 5 dup-pair slots
  __shared__ __align__(16) float sO0[NP * 18];   // 3 rows x 3 dup-pair slots

  const int tid = threadIdx.x;
  const int wrp = tid >> 5, ln = tid & 31;
  const int n = blockIdx.y;
  const int ty = blockIdx.x >> 4, tx = blockIdx.x & 15;
  const int y0 = ty << 3, x0 = tx << 4;

  // ---- mainloop slot addressing ----
  const bool hasx = tid < 256;
  const int ch_ = tid >> 5, t_ = tid & 31;
  const unsigned xd0 = su32(&Xs[ch_ * 128 + 4 * t_]);
  const float* Xn = X + (size_t)n * 64 * 65536;
  const float* xsrc = Xn + (size_t)ch_ * 65536 + (y0 + (t_ >> 2)) * 256 + x0 + ((t_ & 3) << 2);
  const int ka = tid / 66, pa = tid - 66 * ka;
  const int sb_ = tid + 288;
  const bool hasb = sb_ < 528;
  const int kb = sb_ / 66, pb = sb_ - 66 * kb;
  const unsigned wda0 = su32(&Ws[ka * NPP + pa]);
  const unsigned wdb0 = su32(&Ws[kb * NPP + pb]);
  const float* wsa = W + pa * 64 + ka;
  const float* wsb = W + pb * 64 + kb;

  ISSUE_CHUNK(0, 65536); CPA_COMMIT();
  ISSUE_CHUNK(1, 65536); CPA_COMMIT();
  ISSUE_CHUNK(2, 65536); CPA_COMMIT();

  // ---- sO staging (group 3): clamped cpa4 into parity-engineered layouts ----
  {
    const int by2 = (y0 >> 1) - 1, a2 = 8 * tx - 5;
    const float* src = g_O2 + (size_t)n * NP * 16384;
    for (int i = tid; i < NP * 84; i += 288) {
      int p = i / 84, r = i - p * 84;
      int rr = r / 14, cc = r - rr * 14;
      int sy = min(max(by2 + rr, 0), 127);
      int sx = min(max(a2 + cc, 0), 127);
      cpa4(su32(&sO2[i]), src + p * 16384 + sy * 128 + sx);
    }
  }
  {
    const int by1 = (y0 >> 2) - 1, a1 = 4 * tx - 1;
    const float* src = g_O1 + (size_t)n * NP * 4096;
    for (int i = tid; i < NP * 40; i += 288) {
      int p = i / 40, r = i - p * 40;
      int rr = r / 10, s = r - rr * 10;
      int col = a1 + (s >> 1) + (s & 1);
      int sy = min(max(by1 + rr, 0), 63);
      int sx = min(max(col, 0), 63);
      cpa4(su32(&sO1[i]), src + p * 4096 + sy * 64 + sx);
    }
  }
  {
    const int by0 = (y0 >> 3) - 1, a0 = 2 * tx - 1;
    const float* src = g_O0 + (size_t)n * NP * 1024;
    for (int i = tid; i < NP * 18; i += 288) {
      int p = i / 18, r = i - p * 18;
      int rr = r / 6, s = r - rr * 6;
      int col = a0 + (s >> 1) + (s & 1);
      int sy = min(max(by0 + rr, 0), 31);
      int sx = min(max(col, 0), 31);
      cpa4(su32(&sO0[i]), src + p * 1024 + sy * 32 + sx);
    }
  }
  CPA_COMMIT();   // group 3 = staging (drained by iter 2 << epilogue)

  // zero the weight pad slots of all 4 buffers
  if (tid < 192) {
    int b = tid / 48, r = tid - 48 * b;
    int k = r / 6, p = 66 + (r - 6 * k);
    Ws[b * WBUF + k * NPP + p] = 0.0f;
  }

  // ---- stage3 GEMM mainloop (C=64), 4-deep cp.async ring ----
  unsigned long long acc[8][2];
#pragma unroll
  for (int a = 0; a < 8; a++) {
    int p = 8 * wrp + a;
    unsigned long long pk = pack2((p < NP) ? bias[p] : 0.0f);
    acc[a][0] = pk; acc[a][1] = pk;
  }

  for (int i = 0; i < 8; i++) {
    CPA_WAIT(2);
    __syncthreads();
    {
      const float* Wb = Ws + (i & 3) * WBUF;
      const float* Xb = Xs + (i & 3) * XBUF;
      COMPUTE8(Wb, Xb);
    }
    if (i + 3 < 8) ISSUE_CHUNK(i + 3, 65536);
    CPA_COMMIT();
  }
  __syncthreads();  // all compute done; Xs ring now dead -> reuse for signs

  // ---- epilogue: separable bilinear, all taps via aligned LDS.64 ----
  {
    const int r = ln >> 2, qc = ln & 3;
    const float WY2[8] = {.75f, .25f, .75f, .25f, .75f, .25f, .75f, .25f};
    const int   RY2[8] = {0, 1, 1, 2, 2, 3, 3, 4};
    const float WY1[8] = {.625f, .875f, .125f, .375f, .625f, .875f, .125f, .375f};
    const int   RY1[8] = {0, 0, 1, 1, 1, 1, 2, 2};
    const float WY0[8] = {.5625f, .6875f, .8125f, .9375f, .0625f, .1875f, .3125f, .4375f};
    const int   RY0[8] = {0, 0, 0, 0, 1, 1, 1, 1};
    const int ry2 = RY2[r]; const float wy2 = WY2[r];
    const int ry1 = RY1[r]; const float wy1 = WY1[r];
    const int ry0 = RY0[r]; const float wy0 = WY0[r];
    const int w0qc = (qc + 1) >> 1;       // {0,1,1,2}
    const float fx0adj = (qc & 1) ? 0.5f : 0.0f;

    const int   LX2[4] = {0, 1, 1, 2};
    const float FX2[4] = {.75f, .25f, .75f, .25f};
    const int   LX1[4] = {0, 0, 1, 1};
    const float FX1[4] = {.625f, .875f, .125f, .375f};
    const float FX0[4] = {.5625f, .6875f, .8125f, .9375f};

    const int o2 = ry2 * 14 + 2 * qc + 4;
    const int o1 = ry1 * 10 + 2 * qc;
    const int o0 = ry0 * 6 + 2 * w0qc;

    unsigned by[4] = {0, 0, 0, 0};
#pragma unroll
    for (int a = 0; a < 8; a++) {
      int p = 8 * wrp + a;
      float v[4];
      float2 u0 = unpack2(acc[a][0]), u1 = unpack2(acc[a][1]);
      v[0] = u0.x; v[1] = u0.y; v[2] = u1.x; v[3] = u1.y;
      if (p < NP) {
        // L2: 4 y-lerped taps via 4x LDS.64
        const float* A2 = &sO2[p * 84 + o2];
        float2 a01 = *(const float2*)A2;
        float2 a23 = *(const float2*)(A2 + 2);
        float2 b01 = *(const float2*)(A2 + 14);
        float2 b23 = *(const float2*)(A2 + 16);
        float t2[4] = {a01.x + wy2 * (b01.x - a01.x),
                       a01.y + wy2 * (b01.y - a01.y),
                       a23.x + wy2 * (b23.x - a23.x),
                       a23.y + wy2 * (b23.y - a23.y)};
        // L1: 3 y-lerped taps via 4x LDS.64 (dup-pair slots)
        const float* A1 = &sO1[p * 40 + o1];
        float2 c01 = *(const float2*)A1;
        float2 c12 = *(const float2*)(A1 + 2);
        float2 d01 = *(const float2*)(A1 + 10);
        float2 d12 = *(const float2*)(A1 + 12);
        float t1[3] = {c01.x + wy1 * (d01.x - c01.x),
                       c01.y + wy1 * (d01.y - c01.y),
                       c12.y + wy1 * (d12.y - c12.y)};
        // L0: 2 y-lerped taps via 2x LDS.64
        const float* A0 = &sO0[p * 18 + o0];
        float2 e01 = *(const float2*)A0;
        float2 f01 = *(const float2*)(A0 + 6);
        float t0a = e01.x + wy0 * (f01.x - e01.x);
        float t0b = e01.y + wy0 * (f01.y - e01.y);
#pragma unroll
        for (int q = 0; q < 4; q++) {
          v[q] += t2[LX2[q]] + FX2[q] * (t2[LX2[q] + 1] - t2[LX2[q]]);
          v[q] += t1[LX1[q]] + FX1[q] * (t1[LX1[q] + 1] - t1[LX1[q]]);
          float f0 = FX0[q] - fx0adj;
          v[q] += t0a + f0 * (t0b - t0a);
        }
      }
#pragma unroll
      for (int q = 0; q < 4; q++) by[q] |= ((v[q] > 0.0f) ? 1u : 0u) << a;
    }
    unsigned* sS32 = (unsigned*)Xs;
    sS32[wrp * 32 + ln] = by[0] | (by[1] << 8) | (by[2] << 16) | (by[3] << 24);
  }
  __syncthreads();

  // ---- vote via popcount against constant masks, coalesced store ----
  if (tid < 128) {
    const unsigned char* sb8 = (const unsigned char*)Xs;
    unsigned b0 = sb8[tid],           b1 = sb8[128 + tid];
    unsigned b2 = sb8[256 + tid],     b3 = sb8[384 + tid];
    unsigned b4 = sb8[512 + tid],     b5 = sb8[640 + tid];
    unsigned b6 = sb8[768 + tid],     b7 = sb8[896 + tid];
    unsigned b8 = sb8[1024 + tid];
    unsigned sw0 = b0 | (b1 << 8) | (b2 << 16) | (b3 << 24);
    unsigned sw1 = b4 | (b5 << 8) | (b6 << 16) | (b7 << 24);
    unsigned sw2 = b8;
    int row = tid >> 4, col = tid & 15;
    float* op = out + (size_t)n * 12 * 65536 + (y0 + row) * 256 + (x0 + col);
#pragma unroll
    for (int k = 0; k < 12; k++) {
      int4 A = c_MA[k];
      int4 B = c_MB[k];
      int cnt = __popc(sw0 & (unsigned)A.x) + __popc(sw1 & (unsigned)A.y) +
                __popc(sw2 & (unsigned)A.z) - __popc(sw0 & (unsigned)A.w) -
                __popc(sw1 & (unsigned)B.x) - __popc(sw2 & (unsigned)B.y) + k;
      op[(size_t)k << 16] = (float)cnt;
    }
  }
}

// ---------------- launcher ----------------
extern "C" void kernel_launch(void* const* d_in, const int* in_sizes, int n_in,
                              void* d_out, int out_size) {
  const float* st[4] = {0, 0, 0, 0};
  const float* w[4] = {0, 0, 0, 0};
  const float* bb[4] = {0, 0, 0, 0};
  int bc = 0;
  for (int i = 0; i < n_in; i++) {
    switch (in_sizes[i]) {
      case 4194304:  st[0] = (const float*)d_in[i]; break;  // 8*512*32*32
      case 8388608:  st[1] = (const float*)d_in[i]; break;  // 8*256*64*64
      case 16777216: st[2] = (const float*)d_in[i]; break;  // 8*128*128*128
      case 33554432: st[3] = (const float*)d_in[i]; break;  // 8*64*256*256
      case 33792: w[0] = (const float*)d_in[i]; break;      // 66*512
      case 16896: w[1] = (const float*)d_in[i]; break;      // 66*256
      case 8448:  w[2] = (const float*)d_in[i]; break;      // 66*128
      case 4224:  w[3] = (const float*)d_in[i]; break;      // 66*64
      case 66:
        if (bc < 4) bb[bc++] = (const float*)d_in[i];       // b0..b3 in order
        break;
      default: break;  // last_only (==1 always per setup_inputs)
    }
  }

  conv_all<<<1344, 288>>>(st[0], st[1], st[2], w[0], w[1], w[2],
                          bb[0], bb[1], bb[2]);
  fused_kernel<<<dim3(512, 8), 288>>>(st[3], w[3], bb[3], (float*)d_out);
}

// round 11
// speedup vs baseline: 3.4996x; 1.0329x over previous
#include <cuda_runtime.h>

#define NP  66
#define NPP 72

// ---------------- scratch (no allocations allowed) ----------------
// conv outputs, PIXEL-MAJOR: [n][px][72]  (pairs 66..71 are pad)
__device__ __align__(16) float g_O0[8 * 32 * 32 * NPP];
__device__ __align__(16) float g_O1[8 * 64 * 64 * NPP];
__device__ __align__(16) float g_O2[8 * 128 * 128 * NPP];

// Precomputed OvO vote masks over the 66 pairs (+pad bits always 0).
// c_MA[k] = {Imask word0, word1, word2, Jmask word0}
// c_MB[k] = {Jmask word1, word2, 0, 0}
__constant__ int4 c_MA[12] = {
  {0x000007FF, 0x00000000, 0x0, 0x00000000},
  {0x001FF800, 0x00000000, 0x0, 0x00000001},
  {0x3FE00000, 0x00000000, 0x0, 0x00000802},
  {(int)0xC0000000, 0x0000003F, 0x0, 0x00201004},
  {0x00000000, 0x00001FC0, 0x0, 0x40402008},
  {0x00000000, 0x0007E000, 0x0, (int)0x80804010},
  {0x00000000, 0x00F80000, 0x0, 0x01008020},
  {0x00000000, 0x0F000000, 0x0, 0x02010040},
  {0x00000000, 0x70000000, 0x0, 0x04020080},
  {0x00000000, (int)0x80000000, 0x1, 0x08040100},
  {0x00000000, 0x00000000, 0x2, 0x10080200},
  {0x00000000, 0x00000000, 0x0, 0x20100400}};
__constant__ int4 c_MB[12] = {
  {0x00000000, 0x0, 0, 0}, {0x00000000, 0x0, 0, 0},
  {0x00000000, 0x0, 0, 0}, {0x00000000, 0x0, 0, 0},
  {0x00000000, 0x0, 0, 0}, {0x00000040, 0x0, 0, 0},
  {0x00002081, 0x0, 0, 0}, {0x00084102, 0x0, 0, 0},
  {0x01108204, 0x0, 0, 0}, {0x12210408, 0x0, 0, 0},
  {(int)0xA4420810, 0x0, 0, 0}, {0x48841020, 0x3, 0, 0}};

// ---------------- helpers ----------------
__device__ __forceinline__ void ffma2(unsigned long long& d,
                                      unsigned long long a,
                                      unsigned long long b) {
  asm("fma.rn.f32x2 %0, %1, %2, %0;" : "+l"(d) : "l"(a), "l"(b));
}
__device__ __forceinline__ unsigned long long pack2(float x) {
  unsigned long long r;
  asm("mov.b64 %0, {%1, %1};" : "=l"(r) : "f"(x));
  return r;
}
__device__ __forceinline__ float2 unpack2(unsigned long long u) {
  float2 r;
  asm("mov.b64 {%0, %1}, %2;" : "=f"(r.x), "=f"(r.y) : "l"(u));
  return r;
}
__device__ __forceinline__ unsigned su32(const void* p) {
  return (unsigned)__cvta_generic_to_shared(p);
}
__device__ __forceinline__ void cpa16(unsigned dst, const void* src) {
  asm volatile("cp.async.cg.shared.global [%0], [%1], 16;" :: "r"(dst), "l"(src));
}
__device__ __forceinline__ void cpa4(unsigned dst, const void* src) {
  asm volatile("cp.async.ca.shared.global [%0], [%1], 4;" :: "r"(dst), "l"(src));
}
#define CPA_COMMIT() asm volatile("cp.async.commit_group;" ::: "memory")
#define CPA_WAIT(n)  asm volatile("cp.async.wait_group %0;" :: "n"(n) : "memory")

__device__ __forceinline__ float4 f4lerp(float4 a, float4 b, float w) {
  float4 r;
  r.x = a.x + w * (b.x - a.x);
  r.y = a.y + w * (b.y - a.y);
  r.z = a.z + w * (b.z - a.z);
  r.w = a.w + w * (b.w - a.w);
  return r;
}
__device__ __forceinline__ void f4acc(float4& d, float4 lo, float4 hi, float w) {
  d.x += lo.x + w * (hi.x - lo.x);
  d.y += lo.y + w * (hi.y - lo.y);
  d.z += lo.z + w * (hi.z - lo.z);
  d.w += lo.w + w * (hi.w - lo.w);
}

#define XBUF (8 * 128)
#define WBUF (8 * NPP)

// compute one 8-channel chunk: warp 'wrp' owns pairs 8wrp..8wrp+7,
// lane 'ln' owns pixels 4ln..4ln+3
#define COMPUTE8(Wb, Xb)                                                       \
  _Pragma("unroll")                                                            \
  for (int k = 0; k < 8; k++) {                                                \
    const float4 wA = *(const float4*)&(Wb)[k * NPP + 8 * wrp];                \
    const float4 wB = *(const float4*)&(Wb)[k * NPP + 8 * wrp + 4];            \
    const ulonglong2 xv = *(const ulonglong2*)&(Xb)[k * 128 + 4 * ln];         \
    unsigned long long w_[8] = {pack2(wA.x), pack2(wA.y), pack2(wA.z),         \
                                pack2(wA.w), pack2(wB.x), pack2(wB.y),         \
                                pack2(wB.z), pack2(wB.w)};                     \
    _Pragma("unroll")                                                          \
    for (int a = 0; a < 8; a++) {                                              \
      ffma2(acc[a][0], w_[a], xv.x);                                           \
      ffma2(acc[a][1], w_[a], xv.y);                                           \
    }                                                                          \
  }

// issue loads of channel-chunk j into ring buffer j&3
#define ISSUE_CHUNK(j, XSTRIDE)                                                \
  do {                                                                         \
    int _b = (j) & 3, _c0 = (j) * 8;                                           \
    if (hasx) cpa16(xd0 + _b * (XBUF * 4), xsrc + (size_t)_c0 * (XSTRIDE));    \
    cpa4(wda0 + _b * (WBUF * 4), wsa + _c0);                                   \
    if (hasb) cpa4(wdb0 + _b * (WBUF * 4), wsb + _c0);                         \
  } while (0)

// ---------------- conv body: 66 pairs x 128 px, 4-deep cp.async ring ---------
template <int C, int SS>
__device__ __forceinline__ void conv_body(const float* __restrict__ X,
                                          const float* __restrict__ W,
                                          const float* __restrict__ bias,
                                          float* __restrict__ Og,
                                          int n, int px0,
                                          float* Ws, float* Xs) {
  const int tid = threadIdx.x;
  const int wrp = tid >> 5, ln = tid & 31;

  unsigned long long acc[8][2];
#pragma unroll
  for (int a = 0; a < 8; a++) {
    int p = 8 * wrp + a;
    unsigned long long pk = pack2((p < NP) ? bias[p] : 0.0f);
    acc[a][0] = pk; acc[a][1] = pk;
  }

  const bool hasx = tid < 256;
  const int ch_ = tid >> 5, t_ = tid & 31;
  const unsigned xd0 = su32(&Xs[ch_ * 128 + 4 * t_]);
  const float* xsrc = X + (size_t)n * C * SS + px0 + (size_t)ch_ * SS + 4 * t_;

  const int ka = tid / 66, pa = tid - 66 * ka;
  const int sb_ = tid + 288;
  const bool hasb = sb_ < 528;
  const int kb = sb_ / 66, pb = sb_ - 66 * kb;
  const unsigned wda0 = su32(&Ws[ka * NPP + pa]);
  const unsigned wdb0 = su32(&Ws[kb * NPP + pb]);
  const float* wsa = W + pa * C + ka;
  const float* wsb = W + pb * C + kb;

  if (tid < 192) {
    int b = tid / 48, r = tid - 48 * b;
    int k = r / 6, p = 66 + (r - 6 * k);
    Ws[b * WBUF + k * NPP + p] = 0.0f;
  }

  ISSUE_CHUNK(0, SS); CPA_COMMIT();
  ISSUE_CHUNK(1, SS); CPA_COMMIT();
  ISSUE_CHUNK(2, SS); CPA_COMMIT();

  const int NIT = C / 8;
  for (int i = 0; i < NIT; i++) {
    CPA_WAIT(2);
    __syncthreads();
    {
      const float* Wb = Ws + (i & 3) * WBUF;
      const float* Xb = Xs + (i & 3) * XBUF;
      COMPUTE8(Wb, Xb);
    }
    if (i + 3 < NIT) ISSUE_CHUNK(i + 3, SS);
    CPA_COMMIT();
  }

  // store PIXEL-MAJOR: [px][72]; pads (66..71) written with zeros/garbage-free
  float* On = Og + ((size_t)n * SS + px0 + 4 * ln) * NPP + 8 * wrp;
#pragma unroll
  for (int j = 0; j < 4; j++) {
    float4 f0, f1;
    {
      float2 u0 = unpack2(acc[0][j >> 1]);
      float2 u1 = unpack2(acc[1][j >> 1]);
      float2 u2 = unpack2(acc[2][j >> 1]);
      float2 u3 = unpack2(acc[3][j >> 1]);
      f0.x = (j & 1) ? u0.y : u0.x;
      f0.y = (j & 1) ? u1.y : u1.x;
      f0.z = (j & 1) ? u2.y : u2.x;
      f0.w = (j & 1) ? u3.y : u3.x;
    }
    {
      float2 u4 = unpack2(acc[4][j >> 1]);
      float2 u5 = unpack2(acc[5][j >> 1]);
      float2 u6 = unpack2(acc[6][j >> 1]);
      float2 u7 = unpack2(acc[7][j >> 1]);
      f1.x = (j & 1) ? u4.y : u4.x;
      f1.y = (j & 1) ? u5.y : u5.x;
      f1.z = (j & 1) ? u6.y : u6.x;
      f1.w = (j & 1) ? u7.y : u7.x;
    }
    *(float4*)&On[(size_t)j * NPP] = f0;
    *(float4*)&On[(size_t)j * NPP + 4] = f1;
  }
}

// ---------------- merged conv for stages 0..2 ----------------
__global__ __launch_bounds__(288, 3) void conv_all(
    const float* __restrict__ s0, const float* __restrict__ s1,
    const float* __restrict__ s2, const float* __restrict__ w0,
    const float* __restrict__ w1, const float* __restrict__ w2,
    const float* __restrict__ b0, const float* __restrict__ b1,
    const float* __restrict__ b2) {
  __shared__ __align__(16) float Ws[4 * WBUF];
  __shared__ __align__(16) float Xs[4 * XBUF];
  int bid = blockIdx.x;
  if (bid < 64) {
    conv_body<512, 32 * 32>(s0, w0, b0, g_O0, bid >> 3, (bid & 7) << 7, Ws, Xs);
  } else if (bid < 320) {
    int q = bid - 64;
    conv_body<256, 64 * 64>(s1, w1, b1, g_O1, q >> 5, (q & 31) << 7, Ws, Xs);
  } else {
    int q = bid - 320;
    conv_body<128, 128 * 128>(s2, w2, b2, g_O2, q >> 7, (q & 127) << 7, Ws, Xs);
  }
}

// ---------------- fused: stage3 conv + bilinear pyramid sum + popc vote ------
// tile = 8 rows x 16 cols; warp = 8 pairs, lane = 4-px quad (row=ln>>2, qc=ln&3)
// sO buffers are CELL-MAJOR: [cell][72] — pair is the fast axis.
__global__ __launch_bounds__(288, 2) void fused_kernel(
    const float* __restrict__ X, const float* __restrict__ W,
    const float* __restrict__ bias, float* __restrict__ out) {
  __shared__ __align__(16) float Ws[4 * WBUF];
  __shared__ __align__(16) float Xs[4 * XBUF];   // reused for sign bytes later
  __shared__ __align__(16) float sO2[60 * NPP];  // 6 rows x 10 cols of cells
  __shared__ __align__(16) float sO1[24 * NPP];  // 4 x 6
  __shared__ __align__(16) float sO0[12 * NPP];  // 3 x 4

  const int tid = threadIdx.x;
  const int wrp = tid >> 5, ln = tid & 31;
  const int n = blockIdx.y;
  const int ty = blockIdx.x >> 4, tx = blockIdx.x & 15;
  const int y0 = ty << 3, x0 = tx << 4;

  // ---- mainloop slot addressing ----
  const bool hasx = tid < 256;
  const int ch_ = tid >> 5, t_ = tid & 31;
  const unsigned xd0 = su32(&Xs[ch_ * 128 + 4 * t_]);
  const float* Xn = X + (size_t)n * 64 * 65536;
  const float* xsrc = Xn + (size_t)ch_ * 65536 + (y0 + (t_ >> 2)) * 256 + x0 + ((t_ & 3) << 2);
  const int ka = tid / 66, pa = tid - 66 * ka;
  const int sb_ = tid + 288;
  const bool hasb = sb_ < 528;
  const int kb = sb_ / 66, pb = sb_ - 66 * kb;
  const unsigned wda0 = su32(&Ws[ka * NPP + pa]);
  const unsigned wdb0 = su32(&Ws[kb * NPP + pb]);
  const float* wsa = W + pa * 64 + ka;
  const float* wsb = W + pb * 64 + kb;

  ISSUE_CHUNK(0, 65536); CPA_COMMIT();
  ISSUE_CHUNK(1, 65536); CPA_COMMIT();
  ISSUE_CHUNK(2, 65536); CPA_COMMIT();

  // ---- sO staging (group 3): cell-major, 17 cpa16 per cell (floats 0..67) ----
  {
    const int by2 = (y0 >> 1) - 1, bx2 = (x0 >> 1) - 1;
    const float* src = g_O2 + (size_t)n * 16384 * NPP;
    for (int i = tid; i < 60 * 17; i += 288) {
      int cell = i / 17, ch = i - cell * 17;
      int row = cell / 10, col = cell - row * 10;
      int sy = min(max(by2 + row, 0), 127);
      int sx = min(max(bx2 + col, 0), 127);
      cpa16(su32(&sO2[cell * NPP + 4 * ch]),
            src + (size_t)(sy * 128 + sx) * NPP + 4 * ch);
    }
  }
  {
    const int by1 = (y0 >> 2) - 1, bx1 = (x0 >> 2) - 1;
    const float* src = g_O1 + (size_t)n * 4096 * NPP;
    for (int i = tid; i < 24 * 17; i += 288) {
      int cell = i / 17, ch = i - cell * 17;
      int row = cell / 6, col = cell - row * 6;
      int sy = min(max(by1 + row, 0), 63);
      int sx = min(max(bx1 + col, 0), 63);
      cpa16(su32(&sO1[cell * NPP + 4 * ch]),
            src + (size_t)(sy * 64 + sx) * NPP + 4 * ch);
    }
  }
  {
    const int by0 = (y0 >> 3) - 1, bx0 = (x0 >> 3) - 1;
    const float* src = g_O0 + (size_t)n * 1024 * NPP;
    for (int i = tid; i < 12 * 17; i += 288) {
      int cell = i / 17, ch = i - cell * 17;
      int row = cell >> 2, col = cell & 3;
      int sy = min(max(by0 + row, 0), 31);
      int sx = min(max(bx0 + col, 0), 31);
      cpa16(su32(&sO0[cell * NPP + 4 * ch]),
            src + (size_t)(sy * 32 + sx) * NPP + 4 * ch);
    }
  }
  CPA_COMMIT();   // group 3 = staging (drained by iter 2 << epilogue)

  // zero the weight pad slots of all 4 buffers
  if (tid < 192) {
    int b = tid / 48, r = tid - 48 * b;
    int k = r / 6, p = 66 + (r - 6 * k);
    Ws[b * WBUF + k * NPP + p] = 0.0f;
  }

  // ---- stage3 GEMM mainloop (C=64), 4-deep cp.async ring ----
  unsigned long long acc[8][2];
#pragma unroll
  for (int a = 0; a < 8; a++) {
    int p = 8 * wrp + a;
    unsigned long long pk = pack2((p < NP) ? bias[p] : 0.0f);
    acc[a][0] = pk; acc[a][1] = pk;
  }

  for (int i = 0; i < 8; i++) {
    CPA_WAIT(2);
    __syncthreads();
    {
      const float* Wb = Ws + (i & 3) * WBUF;
      const float* Xb = Xs + (i & 3) * XBUF;
      COMPUTE8(Wb, Xb);
    }
    if (i + 3 < 8) ISSUE_CHUNK(i + 3, 65536);
    CPA_COMMIT();
  }
  __syncthreads();  // all compute done; Xs ring now dead -> reuse for signs

  // ---- epilogue: bilinear over cell-major sO, float4 across 4 pairs ----
  {
    const int r = ln >> 2, qc = ln & 3;
    const float WY2[8] = {.75f, .25f, .75f, .25f, .75f, .25f, .75f, .25f};
    const int   RY2[8] = {0, 1, 1, 2, 2, 3, 3, 4};
    const float WY1[8] = {.625f, .875f, .125f, .375f, .625f, .875f, .125f, .375f};
    const int   RY1[8] = {0, 0, 1, 1, 1, 1, 2, 2};
    const float WY0[8] = {.5625f, .6875f, .8125f, .9375f, .0625f, .1875f, .3125f, .4375f};
    const int   RY0[8] = {0, 0, 0, 0, 1, 1, 1, 1};
    const int ry2 = RY2[r]; const float wy2 = WY2[r];
    const int ry1 = RY1[r]; const float wy1 = WY1[r];
    const int ry0 = RY0[r]; const float wy0 = WY0[r];
    const int w0qc = (qc + 1) >> 1;       // {0,1,1,2}
    const float fx0adj = (qc & 1) ? 0.5f : 0.0f;

    const int   LX2[4] = {0, 1, 1, 2};
    const float FX2[4] = {.75f, .25f, .75f, .25f};
    const int   LX1[4] = {0, 0, 1, 1};
    const float FX1[4] = {.625f, .875f, .125f, .375f};
    const float FX0[4] = {.5625f, .6875f, .8125f, .9375f};

    const int rb2 = ry2 * 10 + 2 * qc;   // L2 base cell (row, col0)
    const int rb1 = ry1 * 6 + qc;        // L1 base cell
    const int rb0 = ry0 * 4 + w0qc;      // L0 base cell

    unsigned by[4] = {0, 0, 0, 0};
#pragma unroll
    for (int g = 0; g < 2; g++) {
      const int po = 8 * wrp + 4 * g;
      // init v[j] (4 pairs) from accumulators
      float4 v[4];
#pragma unroll
      for (int j = 0; j < 4; j++) {
        float2 u0 = unpack2(acc[4 * g + 0][j >> 1]);
        float2 u1 = unpack2(acc[4 * g + 1][j >> 1]);
        float2 u2 = unpack2(acc[4 * g + 2][j >> 1]);
        float2 u3 = unpack2(acc[4 * g + 3][j >> 1]);
        v[j].x = (j & 1) ? u0.y : u0.x;
        v[j].y = (j & 1) ? u1.y : u1.x;
        v[j].z = (j & 1) ? u2.y : u2.x;
        v[j].w = (j & 1) ? u3.y : u3.x;
      }
      // L2: 4 tap columns
      {
        float4 t[4];
#pragma unroll
        for (int c = 0; c < 4; c++) {
          float4 A = *(const float4*)&sO2[(rb2 + c) * NPP + po];
          float4 B = *(const float4*)&sO2[(rb2 + 10 + c) * NPP + po];
          t[c] = f4lerp(A, B, wy2);
        }
#pragma unroll
        for (int j = 0; j < 4; j++) f4acc(v[j], t[LX2[j]], t[LX2[j] + 1], FX2[j]);
      }
      // L1: 3 tap columns
      {
        float4 t[3];
#pragma unroll
        for (int c = 0; c < 3; c++) {
          float4 A = *(const float4*)&sO1[(rb1 + c) * NPP + po];
          float4 B = *(const float4*)&sO1[(rb1 + 6 + c) * NPP + po];
          t[c] = f4lerp(A, B, wy1);
        }
#pragma unroll
        for (int j = 0; j < 4; j++) f4acc(v[j], t[LX1[j]], t[LX1[j] + 1], FX1[j]);
      }
      // L0: 2 tap columns
      {
        float4 t[2];
#pragma unroll
        for (int c = 0; c < 2; c++) {
          float4 A = *(const float4*)&sO0[(rb0 + c) * NPP + po];
          float4 B = *(const float4*)&sO0[(rb0 + 4 + c) * NPP + po];
          t[c] = f4lerp(A, B, wy0);
        }
#pragma unroll
        for (int j = 0; j < 4; j++) f4acc(v[j], t[0], t[1], FX0[j] - fx0adj);
      }
      // signs -> bits 4g..4g+3
#pragma unroll
      for (int j = 0; j < 4; j++) {
        unsigned bb = ((v[j].x > 0.0f) ? 1u : 0u) |
                      ((v[j].y > 0.0f) ? 2u : 0u) |
                      ((v[j].z > 0.0f) ? 4u : 0u) |
                      ((v[j].w > 0.0f) ? 8u : 0u);
        by[j] |= bb << (4 * g);
      }
    }
    unsigned* sS32 = (unsigned*)Xs;
    sS32[wrp * 32 + ln] = by[0] | (by[1] << 8) | (by[2] << 16) | (by[3] << 24);
  }
  __syncthreads();

  // ---- vote via popcount against constant masks, coalesced store ----
  if (tid < 128) {
    const unsigned char* sb8 = (const unsigned char*)Xs;
    unsigned b0 = sb8[tid],           b1 = sb8[128 + tid];
    unsigned b2 = sb8[256 + tid],     b3 = sb8[384 + tid];
    unsigned b4 = sb8[512 + tid],     b5 = sb8[640 + tid];
    unsigned b6 = sb8[768 + tid],     b7 = sb8[896 + tid];
    unsigned b8 = sb8[1024 + tid];
    unsigned sw0 = b0 | (b1 << 8) | (b2 << 16) | (b3 << 24);
    unsigned sw1 = b4 | (b5 << 8) | (b6 << 16) | (b7 << 24);
    unsigned sw2 = b8;
    int row = tid >> 4, col = tid & 15;
    float* op = out + (size_t)n * 12 * 65536 + (y0 + row) * 256 + (x0 + col);
#pragma unroll
    for (int k = 0; k < 12; k++) {
      int4 A = c_MA[k];
      int4 B = c_MB[k];
      int cnt = __popc(sw0 & (unsigned)A.x) + __popc(sw1 & (unsigned)A.y) +
                __popc(sw2 & (unsigned)A.z) - __popc(sw0 & (unsigned)A.w) -
                __popc(sw1 & (unsigned)B.x) - __popc(sw2 & (unsigned)B.y) + k;
      op[(size_t)k << 16] = (float)cnt;
    }
  }
}

// ---------------- launcher ----------------
extern "C" void kernel_launch(void* const* d_in, const int* in_sizes, int n_in,
                              void* d_out, int out_size) {
  const float* st[4] = {0, 0, 0, 0};
  const float* w[4] = {0, 0, 0, 0};
  const float* bb[4] = {0, 0, 0, 0};
  int bc = 0;
  for (int i = 0; i < n_in; i++) {
    switch (in_sizes[i]) {
      case 4194304:  st[0] = (const float*)d_in[i]; break;  // 8*512*32*32
      case 8388608:  st[1] = (const float*)d_in[i]; break;  // 8*256*64*64
      case 16777216: st[2] = (const float*)d_in[i]; break;  // 8*128*128*128
      case 33554432: st[3] = (const float*)d_in[i]; break;  // 8*64*256*256
      case 33792: w[0] = (const float*)d_in[i]; break;      // 66*512
      case 16896: w[1] = (const float*)d_in[i]; break;      // 66*256
      case 8448:  w[2] = (const float*)d_in[i]; break;      // 66*128
      case 4224:  w[3] = (const float*)d_in[i]; break;      // 66*64
      case 66:
        if (bc < 4) bb[bc++] = (const float*)d_in[i];       // b0..b3 in order
        break;
      default: break;  // last_only (==1 always per setup_inputs)
    }
  }

  conv_all<<<1344, 288>>>(st[0], st[1], st[2], w[0], w[1], w[2],
                          bb[0], bb[1], bb[2]);
  fused_kernel<<<dim3(512, 8), 288>>>(st[3], w[3], bb[3], (float*)d_out);
}

// round 12
// speedup vs baseline: 4.0570x; 1.1593x over previous
#include <cuda_runtime.h>

#define NP  66
#define NPP 72

// ---------------- scratch (no allocations allowed) ----------------
__device__ __align__(16) float g_O0[8 * NP * 32 * 32];
__device__ __align__(16) float g_O1[8 * NP * 64 * 64];
__device__ __align__(16) float g_O2[8 * NP * 128 * 128];

// Precomputed OvO vote masks over the 66 pairs (+pad bits always 0).
__constant__ int4 c_MA[12] = {
  {0x000007FF, 0x00000000, 0x0, 0x00000000},
  {0x001FF800, 0x00000000, 0x0, 0x00000001},
  {0x3FE00000, 0x00000000, 0x0, 0x00000802},
  {(int)0xC0000000, 0x0000003F, 0x0, 0x00201004},
  {0x00000000, 0x00001FC0, 0x0, 0x40402008},
  {0x00000000, 0x0007E000, 0x0, (int)0x80804010},
  {0x00000000, 0x00F80000, 0x0, 0x01008020},
  {0x00000000, 0x0F000000, 0x0, 0x02010040},
  {0x00000000, 0x70000000, 0x0, 0x04020080},
  {0x00000000, (int)0x80000000, 0x1, 0x08040100},
  {0x00000000, 0x00000000, 0x2, 0x10080200},
  {0x00000000, 0x00000000, 0x0, 0x20100400}};
__constant__ int4 c_MB[12] = {
  {0x00000000, 0x0, 0, 0}, {0x00000000, 0x0, 0, 0},
  {0x00000000, 0x0, 0, 0}, {0x00000000, 0x0, 0, 0},
  {0x00000000, 0x0, 0, 0}, {0x00000040, 0x0, 0, 0},
  {0x00002081, 0x0, 0, 0}, {0x00084102, 0x0, 0, 0},
  {0x01108204, 0x0, 0, 0}, {0x12210408, 0x0, 0, 0},
  {(int)0xA4420810, 0x0, 0, 0}, {0x48841020, 0x3, 0, 0}};

// bilinear y-tables (indexed by tile row r) — constant port, not regs/L1
__constant__ float c_WY[24] = {
  .75f, .25f, .75f, .25f, .75f, .25f, .75f, .25f,                  // L2 (f=2)
  .625f, .875f, .125f, .375f, .625f, .875f, .125f, .375f,          // L1 (f=4)
  .5625f, .6875f, .8125f, .9375f, .0625f, .1875f, .3125f, .4375f}; // L0 (f=8)
__constant__ int c_RY[24] = {
  0, 1, 1, 2, 2, 3, 3, 4,
  0, 0, 1, 1, 1, 1, 2, 2,
  0, 0, 0, 0, 1, 1, 1, 1};

// ---------------- helpers ----------------
__device__ __forceinline__ void ffma2(unsigned long long& d,
                                      unsigned long long a,
                                      unsigned long long b) {
  asm("fma.rn.f32x2 %0, %1, %2, %0;" : "+l"(d) : "l"(a), "l"(b));
}
__device__ __forceinline__ unsigned long long pack2(float x) {
  unsigned long long r;
  asm("mov.b64 %0, {%1, %1};" : "=l"(r) : "f"(x));
  return r;
}
__device__ __forceinline__ float2 unpack2(unsigned long long u) {
  float2 r;
  asm("mov.b64 {%0, %1}, %2;" : "=f"(r.x), "=f"(r.y) : "l"(u));
  return r;
}
__device__ __forceinline__ unsigned su32(const void* p) {
  return (unsigned)__cvta_generic_to_shared(p);
}
__device__ __forceinline__ void cpa16(unsigned dst, const void* src) {
  asm volatile("cp.async.cg.shared.global [%0], [%1], 16;" :: "r"(dst), "l"(src));
}
__device__ __forceinline__ void cpa4(unsigned dst, const void* src) {
  asm volatile("cp.async.ca.shared.global [%0], [%1], 4;" :: "r"(dst), "l"(src));
}
#define CPA_COMMIT() asm volatile("cp.async.commit_group;" ::: "memory")
#define CPA_WAIT(n)  asm volatile("cp.async.wait_group %0;" :: "n"(n) : "memory")

#define XBUF (8 * 128)
#define WBUF (8 * NPP)

// compute one 8-channel chunk, split in two 4-pair halves (lower reg pressure)
#define COMPUTE8(Wb, Xb)                                                       \
  _Pragma("unroll")                                                            \
  for (int k = 0; k < 8; k++) {                                                \
    const ulonglong2 xv = *(const ulonglong2*)&(Xb)[k * 128 + 4 * ln];         \
    {                                                                          \
      const float4 wA = *(const float4*)&(Wb)[k * NPP + 8 * wrp];              \
      unsigned long long w0 = pack2(wA.x), w1 = pack2(wA.y);                   \
      unsigned long long w2 = pack2(wA.z), w3 = pack2(wA.w);                   \
      ffma2(acc[0][0], w0, xv.x); ffma2(acc[0][1], w0, xv.y);                  \
      ffma2(acc[1][0], w1, xv.x); ffma2(acc[1][1], w1, xv.y);                  \
      ffma2(acc[2][0], w2, xv.x); ffma2(acc[2][1], w2, xv.y);                  \
      ffma2(acc[3][0], w3, xv.x); ffma2(acc[3][1], w3, xv.y);                  \
    }                                                                          \
    {                                                                          \
      const float4 wB = *(const float4*)&(Wb)[k * NPP + 8 * wrp + 4];          \
      unsigned long long w4 = pack2(wB.x), w5 = pack2(wB.y);                   \
      unsigned long long w6 = pack2(wB.z), w7 = pack2(wB.w);                   \
      ffma2(acc[4][0], w4, xv.x); ffma2(acc[4][1], w4, xv.y);                  \
      ffma2(acc[5][0], w5, xv.x); ffma2(acc[5][1], w5, xv.y);                  \
      ffma2(acc[6][0], w6, xv.x); ffma2(acc[6][1], w6, xv.y);                  \
      ffma2(acc[7][0], w7, xv.x); ffma2(acc[7][1], w7, xv.y);                  \
    }                                                                          \
  }

// issue loads of channel-chunk j into ring buffer j&3
#define ISSUE_CHUNK(j, XSTRIDE)                                                \
  do {                                                                         \
    int _b = (j) & 3, _c0 = (j) * 8;                                           \
    if (hasx) cpa16(xd0 + _b * (XBUF * 4), xsrc + (size_t)_c0 * (XSTRIDE));    \
    cpa4(wda0 + _b * (WBUF * 4), wsa + _c0);                                   \
    if (hasb) cpa4(wdb0 + _b * (WBUF * 4), wsb + _c0);                         \
  } while (0)

// ---------------- conv body: 66 pairs x 128 px, 4-deep cp.async ring ---------
template <int C, int SS>
__device__ __forceinline__ void conv_body(const float* __restrict__ X,
                                          const float* __restrict__ W,
                                          const float* __restrict__ bias,
                                          float* __restrict__ Og,
                                          int n, int px0,
                                          float* Ws, float* Xs) {
  const int tid = threadIdx.x;
  const int wrp = tid >> 5, ln = tid & 31;

  unsigned long long acc[8][2];
#pragma unroll
  for (int a = 0; a < 8; a++) {
    int p = 8 * wrp + a;
    unsigned long long pk = pack2((p < NP) ? bias[p] : 0.0f);
    acc[a][0] = pk; acc[a][1] = pk;
  }

  const bool hasx = tid < 256;
  const int ch_ = tid >> 5, t_ = tid & 31;
  const unsigned xd0 = su32(&Xs[ch_ * 128 + 4 * t_]);
  const float* xsrc = X + (size_t)n * C * SS + px0 + (size_t)ch_ * SS + 4 * t_;

  const int ka = tid / 66, pa = tid - 66 * ka;
  const int sb_ = tid + 288;
  const bool hasb = sb_ < 528;
  const int kb = sb_ / 66, pb = sb_ - 66 * kb;
  const unsigned wda0 = su32(&Ws[ka * NPP + pa]);
  const unsigned wdb0 = su32(&Ws[kb * NPP + pb]);
  const float* wsa = W + pa * C + ka;
  const float* wsb = W + pb * C + kb;

  if (tid < 192) {
    int b = tid / 48, r = tid - 48 * b;
    int k = r / 6, p = 66 + (r - 6 * k);
    Ws[b * WBUF + k * NPP + p] = 0.0f;
  }

  ISSUE_CHUNK(0, SS); CPA_COMMIT();
  ISSUE_CHUNK(1, SS); CPA_COMMIT();
  ISSUE_CHUNK(2, SS); CPA_COMMIT();

  const int NIT = C / 8;
  for (int i = 0; i < NIT; i++) {
    CPA_WAIT(2);
    __syncthreads();
    {
      const float* Wb = Ws + (i & 3) * WBUF;
      const float* Xb = Xs + (i & 3) * XBUF;
      COMPUTE8(Wb, Xb);
    }
    if (i + 3 < NIT) ISSUE_CHUNK(i + 3, SS);
    CPA_COMMIT();
  }

  float* On = Og + (size_t)n * NP * SS + px0 + 4 * ln;
#pragma unroll
  for (int a = 0; a < 8; a++) {
    int p = 8 * wrp + a;
    if (p < NP) {
      ulonglong2 v;
      v.x = acc[a][0]; v.y = acc[a][1];
      *(ulonglong2*)&On[(size_t)p * SS] = v;
    }
  }
}

// ---------------- merged conv for stages 0..2 ----------------
__global__ __launch_bounds__(288, 3) void conv_all(
    const float* __restrict__ s0, const float* __restrict__ s1,
    const float* __restrict__ s2, const float* __restrict__ w0,
    const float* __restrict__ w1, const float* __restrict__ w2,
    const float* __restrict__ b0, const float* __restrict__ b1,
    const float* __restrict__ b2) {
  __shared__ __align__(16) float Ws[4 * WBUF];
  __shared__ __align__(16) float Xs[4 * XBUF];
  int bid = blockIdx.x;
  if (bid < 64) {
    conv_body<512, 32 * 32>(s0, w0, b0, g_O0, bid >> 3, (bid & 7) << 7, Ws, Xs);
  } else if (bid < 320) {
    int q = bid - 64;
    conv_body<256, 64 * 64>(s1, w1, b1, g_O1, q >> 5, (q & 31) << 7, Ws, Xs);
  } else {
    int q = bid - 320;
    conv_body<128, 128 * 128>(s2, w2, b2, g_O2, q >> 7, (q & 127) << 7, Ws, Xs);
  }
}

// ---------------- fused: stage3 conv + bilinear pyramid sum + popc vote ------
// tile = 8 rows x 16 cols; warp = 8 pairs, lane = 4-px quad (row=ln>>2, qc=ln&3)
__global__ __launch_bounds__(288, 3) void fused_kernel(
    const float* __restrict__ X, const float* __restrict__ W,
    const float* __restrict__ bias, float* __restrict__ out) {
  __shared__ __align__(16) float Ws[4 * WBUF];
  __shared__ __align__(16) float Xs[4 * XBUF];   // reused for sign bytes later
  __shared__ __align__(16) float sO2[NP * 96];   // 6 rows x 16 (base col 8tx-4)
  __shared__ __align__(16) float sO1[NP * 48];   // 4 rows x 12 (base col 4tx-4)
  __shared__ __align__(16) float sO0[NP * 24];   // 3 rows x 8 (base a0x)

  const int tid = threadIdx.x;
  const int wrp = tid >> 5, ln = tid & 31;
  const int n = blockIdx.y;
  const int ty = blockIdx.x >> 4, tx = blockIdx.x & 15;
  const int y0 = ty << 3, x0 = tx << 4;

  // ---- mainloop slot addressing ----
  const bool hasx = tid < 256;
  const int ch_ = tid >> 5, t_ = tid & 31;
  const unsigned xd0 = su32(&Xs[ch_ * 128 + 4 * t_]);
  const float* Xn = X + (size_t)n * 64 * 65536;
  const float* xsrc = Xn + (size_t)ch_ * 65536 + (y0 + (t_ >> 2)) * 256 + x0 + ((t_ & 3) << 2);
  const int ka = tid / 66, pa = tid - 66 * ka;
  const int sb_ = tid + 288;
  const bool hasb = sb_ < 528;
  const int kb = sb_ / 66, pb = sb_ - 66 * kb;
  const unsigned wda0 = su32(&Ws[ka * NPP + pa]);
  const unsigned wdb0 = su32(&Ws[kb * NPP + pb]);
  const float* wsa = W + pa * 64 + ka;
  const float* wsb = W + pb * 64 + kb;

  ISSUE_CHUNK(0, 65536); CPA_COMMIT();
  ISSUE_CHUNK(1, 65536); CPA_COMMIT();
  ISSUE_CHUNK(2, 65536); CPA_COMMIT();

  // ---- sO staging (group 3) ----
  const int by2 = (y0 >> 1) - 1, a2 = 8 * tx - 4;
  const int by1 = (y0 >> 2) - 1, a1 = 4 * tx - 4;
  const int by0 = (y0 >> 3) - 1;
  const int bx0 = 2 * tx - 1, a0x = bx0 & ~3, off0 = bx0 & 3;
  const float* s2g = g_O2 + (size_t)n * NP * 16384;
  const float* s1g = g_O1 + (size_t)n * NP * 4096;
  const float* s0g = g_O0 + (size_t)n * NP * 1024;

  if (tx >= 1 && tx <= 14) {
    for (int i = tid; i < NP * 24; i += 288) {         // O2: 6 rows x 4 chunks
      int p = i / 24, r = i - p * 24;
      int rr = r >> 2, c4 = (r & 3) << 2;
      int sy = min(max(by2 + rr, 0), 127);
      cpa16(su32(&sO2[p * 96 + rr * 16 + c4]), s2g + p * 16384 + sy * 128 + a2 + c4);
    }
    for (int i = tid; i < NP * 12; i += 288) {         // O1: 4 rows x 3 chunks
      int p = i / 12, r = i - p * 12;
      int rr = r / 3, c4 = (r - rr * 3) << 2;
      int sy = min(max(by1 + rr, 0), 63);
      cpa16(su32(&sO1[p * 48 + rr * 12 + c4]), s1g + p * 4096 + sy * 64 + a1 + c4);
    }
    for (int i = tid; i < NP * 6; i += 288) {          // O0: 3 rows x 2 chunks
      int p = i / 6, r = i - p * 6;
      int rr = r >> 1, c4 = (r & 1) << 2;
      int sy = min(max(by0 + rr, 0), 31);
      cpa16(su32(&sO0[p * 24 + rr * 8 + c4]), s0g + p * 1024 + sy * 32 + a0x + c4);
    }
  } else {  // edge tiles: scalar clamped staging (same layouts)
    for (int i = tid; i < NP * 96; i += 288) {
      int p = i / 96, r = i - p * 96;
      int rr = r >> 4, c = r & 15;
      int sy = min(max(by2 + rr, 0), 127);
      int sx = min(max(a2 + c, 0), 127);
      cpa4(su32(&sO2[p * 96 + rr * 16 + c]), s2g + p * 16384 + sy * 128 + sx);
    }
    for (int i = tid; i < NP * 48; i += 288) {
      int p = i / 48, r = i - p * 48;
      int rr = r / 12, c = r - rr * 12;
      int sy = min(max(by1 + rr, 0), 63);
      int sx = min(max(a1 + c, 0), 63);
      cpa4(su32(&sO1[p * 48 + rr * 12 + c]), s1g + p * 4096 + sy * 64 + sx);
    }
    for (int i = tid; i < NP * 24; i += 288) {
      int p = i / 24, r = i - p * 24;
      int rr = r >> 3, c = r & 7;
      int sy = min(max(by0 + rr, 0), 31);
      int sx = min(max(a0x + c, 0), 31);
      cpa4(su32(&sO0[p * 24 + rr * 8 + c]), s0g + p * 1024 + sy * 32 + sx);
    }
  }
  CPA_COMMIT();   // group 3 = staging

  // zero the weight pad slots of all 4 buffers
  if (tid < 192) {
    int b = tid / 48, r = tid - 48 * b;
    int k = r / 6, p = 66 + (r - 6 * k);
    Ws[b * WBUF + k * NPP + p] = 0.0f;
  }

  // ---- stage3 GEMM mainloop (C=64), 4-deep cp.async ring ----
  unsigned long long acc[8][2];
#pragma unroll
  for (int a = 0; a < 8; a++) {
    int p = 8 * wrp + a;
    unsigned long long pk = pack2((p < NP) ? bias[p] : 0.0f);
    acc[a][0] = pk; acc[a][1] = pk;
  }

  for (int i = 0; i < 8; i++) {
    CPA_WAIT(2);
    __syncthreads();
    {
      const float* Wb = Ws + (i & 3) * WBUF;
      const float* Xb = Xs + (i & 3) * XBUF;
      COMPUTE8(Wb, Xb);
    }
    if (i + 3 < 8) ISSUE_CHUNK(i + 3, 65536);
    CPA_COMMIT();
  }
  __syncthreads();  // all compute done; Xs ring now dead -> reuse for signs

  // ---- epilogue: separable bilinear (quad-shared taps) + sign bytes ----
  {
    const int r = ln >> 2, qc = ln & 3;
    const int ry2 = c_RY[r];      const float wy2 = c_WY[r];
    const int ry1 = c_RY[8 + r];  const float wy1 = c_WY[8 + r];
    const int ry0 = c_RY[16 + r]; const float wy0 = c_WY[16 + r];
    const int w0qc = (qc + 1) >> 1;       // {0,1,1,2}
    const float fx0adj = (qc & 1) ? 0.5f : 0.0f;

    const int   LX2[4] = {0, 1, 1, 2};
    const float FX2[4] = {.75f, .25f, .75f, .25f};
    const int   LX1[4] = {0, 0, 1, 1};
    const float FX1[4] = {.625f, .875f, .125f, .375f};
    const float FX0[4] = {.5625f, .6875f, .8125f, .9375f};

    const int o2 = ry2 * 16 + 3 + 2 * qc;
    const int o1 = ry1 * 12 + 3 + qc;
    const int o0 = ry0 * 8 + off0 + w0qc;

    unsigned by[4] = {0, 0, 0, 0};
#pragma unroll
    for (int a = 0; a < 8; a++) {
      int p = 8 * wrp + a;
      float v[4];
      float2 u0 = unpack2(acc[a][0]), u1 = unpack2(acc[a][1]);
      v[0] = u0.x; v[1] = u0.y; v[2] = u1.x; v[3] = u1.y;
      if (p < NP) {
        const float* A2 = &sO2[p * 96 + o2];
        float t2[4];
#pragma unroll
        for (int t = 0; t < 4; t++) t2[t] = A2[t] + wy2 * (A2[t + 16] - A2[t]);
        const float* A1 = &sO1[p * 48 + o1];
        float t1[3];
#pragma unroll
        for (int t = 0; t < 3; t++) t1[t] = A1[t] + wy1 * (A1[t + 12] - A1[t]);
        const float* A0 = &sO0[p * 24 + o0];
        float t0a = A0[0] + wy0 * (A0[8] - A0[0]);
        float t0b = A0[1] + wy0 * (A0[9] - A0[1]);
#pragma unroll
        for (int q = 0; q < 4; q++) {
          v[q] += t2[LX2[q]] + FX2[q] * (t2[LX2[q] + 1] - t2[LX2[q]]);
          v[q] += t1[LX1[q]] + FX1[q] * (t1[LX1[q] + 1] - t1[LX1[q]]);
          float f0 = FX0[q] - fx0adj;
          v[q] += t0a + f0 * (t0b - t0a);
        }
      }
#pragma unroll
      for (int q = 0; q < 4; q++) by[q] |= ((v[q] > 0.0f) ? 1u : 0u) << a;
    }
    unsigned* sS32 = (unsigned*)Xs;
    sS32[wrp * 32 + ln] = by[0] | (by[1] << 8) | (by[2] << 16) | (by[3] << 24);
  }
  __syncthreads();

  // ---- vote via popcount against constant masks, coalesced store ----
  if (tid < 128) {
    const unsigned char* sb8 = (const unsigned char*)Xs;
    unsigned b0 = sb8[tid],           b1 = sb8[128 + tid];
    unsigned b2 = sb8[256 + tid],     b3 = sb8[384 + tid];
    unsigned b4 = sb8[512 + tid],     b5 = sb8[640 + tid];
    unsigned b6 = sb8[768 + tid],     b7 = sb8[896 + tid];
    unsigned b8 = sb8[1024 + tid];
    unsigned sw0 = b0 | (b1 << 8) | (b2 << 16) | (b3 << 24);
    unsigned sw1 = b4 | (b5 << 8) | (b6 << 16) | (b7 << 24);
    unsigned sw2 = b8;
    int row = tid >> 4, col = tid & 15;
    float* op = out + (size_t)n * 12 * 65536 + (y0 + row) * 256 + (x0 + col);
#pragma unroll
    for (int k = 0; k < 12; k++) {
      int4 A = c_MA[k];
      int4 B = c_MB[k];
      int cnt = __popc(sw0 & (unsigned)A.x) + __popc(sw1 & (unsigned)A.y) +
                __popc(sw2 & (unsigned)A.z) - __popc(sw0 & (unsigned)A.w) -
                __popc(sw1 & (unsigned)B.x) - __popc(sw2 & (unsigned)B.y) + k;
      op[(size_t)k << 16] = (float)cnt;
    }
  }
}

// ---------------- launcher ----------------
extern "C" void kernel_launch(void* const* d_in, const int* in_sizes, int n_in,
                              void* d_out, int out_size) {
  const float* st[4] = {0, 0, 0, 0};
  const float* w[4] = {0, 0, 0, 0};
  const float* bb[4] = {0, 0, 0, 0};
  int bc = 0;
  for (int i = 0; i < n_in; i++) {
    switch (in_sizes[i]) {
      case 4194304:  st[0] = (const float*)d_in[i]; break;  // 8*512*32*32
      case 8388608:  st[1] = (const float*)d_in[i]; break;  // 8*256*64*64
      case 16777216: st[2] = (const float*)d_in[i]; break;  // 8*128*128*128
      case 33554432: st[3] = (const float*)d_in[i]; break;  // 8*64*256*256
      case 33792: w[0] = (const float*)d_in[i]; break;      // 66*512
      case 16896: w[1] = (const float*)d_in[i]; break;      // 66*256
      case 8448:  w[2] = (const float*)d_in[i]; break;      // 66*128
      case 4224:  w[3] = (const float*)d_in[i]; break;      // 66*64
      case 66:
        if (bc < 4) bb[bc++] = (const float*)d_in[i];       // b0..b3 in order
        break;
      default: break;  // last_only (==1 always per setup_inputs)
    }
  }

  // prefer max shared carveout so 3 x 70KB fused CTAs fit (idempotent, no alloc)
  cudaFuncSetAttribute(fused_kernel,
                       cudaFuncAttributePreferredSharedMemoryCarveout, 100);
  cudaFuncSetAttribute(conv_all,
                       cudaFuncAttributePreferredSharedMemoryCarveout, 100);

  conv_all<<<1344, 288>>>(st[0], st[1], st[2], w[0], w[1], w[2],
                          bb[0], bb[1], bb[2]);
  fused_kernel<<<dim3(512, 8), 288>>>(st[3], w[3], bb[3], (float*)d_out);
}

// round 13
// speedup vs baseline: 4.1242x; 1.0166x over previous
#include <cuda_runtime.h>

#define NP  66
#define NPP 72

// ---------------- scratch (no allocations allowed) ----------------
__device__ __align__(16) float g_O0[8 * NP * 32 * 32];
__device__ __align__(16) float g_O1[8 * NP * 64 * 64];
__device__ __align__(16) float g_O2[8 * NP * 128 * 128];

// Precomputed OvO vote masks over the 66 pairs (+pad bits always 0).
__constant__ int4 c_MA[12] = {
  {0x000007FF, 0x00000000, 0x0, 0x00000000},
  {0x001FF800, 0x00000000, 0x0, 0x00000001},
  {0x3FE00000, 0x00000000, 0x0, 0x00000802},
  {(int)0xC0000000, 0x0000003F, 0x0, 0x00201004},
  {0x00000000, 0x00001FC0, 0x0, 0x40402008},
  {0x00000000, 0x0007E000, 0x0, (int)0x80804010},
  {0x00000000, 0x00F80000, 0x0, 0x01008020},
  {0x00000000, 0x0F000000, 0x0, 0x02010040},
  {0x00000000, 0x70000000, 0x0, 0x04020080},
  {0x00000000, (int)0x80000000, 0x1, 0x08040100},
  {0x00000000, 0x00000000, 0x2, 0x10080200},
  {0x00000000, 0x00000000, 0x0, 0x20100400}};
__constant__ int4 c_MB[12] = {
  {0x00000000, 0x0, 0, 0}, {0x00000000, 0x0, 0, 0},
  {0x00000000, 0x0, 0, 0}, {0x00000000, 0x0, 0, 0},
  {0x00000000, 0x0, 0, 0}, {0x00000040, 0x0, 0, 0},
  {0x00002081, 0x0, 0, 0}, {0x00084102, 0x0, 0, 0},
  {0x01108204, 0x0, 0, 0}, {0x12210408, 0x0, 0, 0},
  {(int)0xA4420810, 0x0, 0, 0}, {0x48841020, 0x3, 0, 0}};

// bilinear y-tables (indexed by tile row r) — constant port, not regs/L1
__constant__ float c_WY[24] = {
  .75f, .25f, .75f, .25f, .75f, .25f, .75f, .25f,                  // L2 (f=2)
  .625f, .875f, .125f, .375f, .625f, .875f, .125f, .375f,          // L1 (f=4)
  .5625f, .6875f, .8125f, .9375f, .0625f, .1875f, .3125f, .4375f}; // L0 (f=8)
__constant__ int c_RY[24] = {
  0, 1, 1, 2, 2, 3, 3, 4,
  0, 0, 1, 1, 1, 1, 2, 2,
  0, 0, 0, 0, 1, 1, 1, 1};

// ---------------- helpers ----------------
__device__ __forceinline__ void ffma2(unsigned long long& d,
                                      unsigned long long a,
                                      unsigned long long b) {
  asm("fma.rn.f32x2 %0, %1, %2, %0;" : "+l"(d) : "l"(a), "l"(b));
}
__device__ __forceinline__ unsigned long long pack2(float x) {
  unsigned long long r;
  asm("mov.b64 %0, {%1, %1};" : "=l"(r) : "f"(x));
  return r;
}
__device__ __forceinline__ float2 unpack2(unsigned long long u) {
  float2 r;
  asm("mov.b64 {%0, %1}, %2;" : "=f"(r.x), "=f"(r.y) : "l"(u));
  return r;
}
__device__ __forceinline__ unsigned su32(const void* p) {
  return (unsigned)__cvta_generic_to_shared(p);
}
__device__ __forceinline__ void cpa16(unsigned dst, const void* src) {
  asm volatile("cp.async.cg.shared.global [%0], [%1], 16;" :: "r"(dst), "l"(src));
}
__device__ __forceinline__ void cpa4(unsigned dst, const void* src) {
  asm volatile("cp.async.ca.shared.global [%0], [%1], 4;" :: "r"(dst), "l"(src));
}
#define CPA_COMMIT() asm volatile("cp.async.commit_group;" ::: "memory")
#define CPA_WAIT(n)  asm volatile("cp.async.wait_group %0;" :: "n"(n) : "memory")

#define XBUF (8 * 128)
#define WBUF (8 * NPP)

// compute one 8-channel chunk, split in two 4-pair halves (lower reg pressure)
#define COMPUTE8(Wb, Xb)                                                       \
  _Pragma("unroll")                                                            \
  for (int k = 0; k < 8; k++) {                                                \
    const ulonglong2 xv = *(const ulonglong2*)&(Xb)[k * 128 + 4 * ln];         \
    {                                                                          \
      const float4 wA = *(const float4*)&(Wb)[k * NPP + 8 * wrp];              \
      unsigned long long w0 = pack2(wA.x), w1 = pack2(wA.y);                   \
      unsigned long long w2 = pack2(wA.z), w3 = pack2(wA.w);                   \
      ffma2(acc[0][0], w0, xv.x); ffma2(acc[0][1], w0, xv.y);                  \
      ffma2(acc[1][0], w1, xv.x); ffma2(acc[1][1], w1, xv.y);                  \
      ffma2(acc[2][0], w2, xv.x); ffma2(acc[2][1], w2, xv.y);                  \
      ffma2(acc[3][0], w3, xv.x); ffma2(acc[3][1], w3, xv.y);                  \
    }                                                                          \
    {                                                                          \
      const float4 wB = *(const float4*)&(Wb)[k * NPP + 8 * wrp + 4];          \
      unsigned long long w4 = pack2(wB.x), w5 = pack2(wB.y);                   \
      unsigned long long w6 = pack2(wB.z), w7 = pack2(wB.w);                   \
      ffma2(acc[4][0], w4, xv.x); ffma2(acc[4][1], w4, xv.y);                  \
      ffma2(acc[5][0], w5, xv.x); ffma2(acc[5][1], w5, xv.y);                  \
      ffma2(acc[6][0], w6, xv.x); ffma2(acc[6][1], w6, xv.y);                  \
      ffma2(acc[7][0], w7, xv.x); ffma2(acc[7][1], w7, xv.y);                  \
    }                                                                          \
  }

// issue loads of channel-chunk j into ring buffer j&3
#define ISSUE_CHUNK(j, XSTRIDE)                                                \
  do {                                                                         \
    int _b = (j) & 3, _c0 = (j) * 8;                                           \
    if (hasx) cpa16(xd0 + _b * (XBUF * 4), xsrc + (size_t)_c0 * (XSTRIDE));    \
    cpa4(wda0 + _b * (WBUF * 4), wsa + _c0);                                   \
    if (hasb) cpa4(wdb0 + _b * (WBUF * 4), wsb + _c0);                         \
  } while (0)

// ---------------- conv body: 66 pairs x 128 px, 4-deep cp.async ring ---------
template <int C, int SS>
__device__ __forceinline__ void conv_body(const float* __restrict__ X,
                                          const float* __restrict__ W,
                                          const float* __restrict__ bias,
                                          float* __restrict__ Og,
                                          int n, int px0,
                                          float* Ws, float* Xs) {
  const int tid = threadIdx.x;
  const int wrp = tid >> 5, ln = tid & 31;

  unsigned long long acc[8][2];
#pragma unroll
  for (int a = 0; a < 8; a++) {
    int p = 8 * wrp + a;
    unsigned long long pk = pack2((p < NP) ? bias[p] : 0.0f);
    acc[a][0] = pk; acc[a][1] = pk;
  }

  const bool hasx = tid < 256;
  const int ch_ = tid >> 5, t_ = tid & 31;
  const unsigned xd0 = su32(&Xs[ch_ * 128 + 4 * t_]);
  const float* xsrc = X + (size_t)n * C * SS + px0 + (size_t)ch_ * SS + 4 * t_;

  const int ka = tid / 66, pa = tid - 66 * ka;
  const int sb_ = tid + 288;
  const bool hasb = sb_ < 528;
  const int kb = sb_ / 66, pb = sb_ - 66 * kb;
  const unsigned wda0 = su32(&Ws[ka * NPP + pa]);
  const unsigned wdb0 = su32(&Ws[kb * NPP + pb]);
  const float* wsa = W + pa * C + ka;
  const float* wsb = W + pb * C + kb;

  if (tid < 192) {
    int b = tid / 48, r = tid - 48 * b;
    int k = r / 6, p = 66 + (r - 6 * k);
    Ws[b * WBUF + k * NPP + p] = 0.0f;
  }

  ISSUE_CHUNK(0, SS); CPA_COMMIT();
  ISSUE_CHUNK(1, SS); CPA_COMMIT();
  ISSUE_CHUNK(2, SS); CPA_COMMIT();

  const int NIT = C / 8;
  for (int i = 0; i < NIT; i++) {
    CPA_WAIT(2);
    __syncthreads();
    {
      const float* Wb = Ws + (i & 3) * WBUF;
      const float* Xb = Xs + (i & 3) * XBUF;
      COMPUTE8(Wb, Xb);
    }
    if (i + 3 < NIT) ISSUE_CHUNK(i + 3, SS);
    CPA_COMMIT();
  }

  float* On = Og + (size_t)n * NP * SS + px0 + 4 * ln;
#pragma unroll
  for (int a = 0; a < 8; a++) {
    int p = 8 * wrp + a;
    if (p < NP) {
      ulonglong2 v;
      v.x = acc[a][0]; v.y = acc[a][1];
      *(ulonglong2*)&On[(size_t)p * SS] = v;
    }
  }
}

// ---------------- merged conv for stages 0..2 ----------------
__global__ __launch_bounds__(288, 3) void conv_all(
    const float* __restrict__ s0, const float* __restrict__ s1,
    const float* __restrict__ s2, const float* __restrict__ w0,
    const float* __restrict__ w1, const float* __restrict__ w2,
    const float* __restrict__ b0, const float* __restrict__ b1,
    const float* __restrict__ b2) {
  __shared__ __align__(16) float Ws[4 * WBUF];
  __shared__ __align__(16) float Xs[4 * XBUF];
  int bid = blockIdx.x;
  if (bid < 64) {
    conv_body<512, 32 * 32>(s0, w0, b0, g_O0, bid >> 3, (bid & 7) << 7, Ws, Xs);
  } else if (bid < 320) {
    int q = bid - 64;
    conv_body<256, 64 * 64>(s1, w1, b1, g_O1, q >> 5, (q & 31) << 7, Ws, Xs);
  } else {
    int q = bid - 320;
    conv_body<128, 128 * 128>(s2, w2, b2, g_O2, q >> 7, (q & 127) << 7, Ws, Xs);
  }
}

// ---------------- fused: stage3 conv + bilinear pyramid sum + popc vote ------
// tile = 8 rows x 16 cols; warp = 8 pairs, lane = 4-px quad (row=ln>>2, qc=ln&3)
// sO2 rows padded to stride 20 (vs data width 16) to break LDS bank cycling.
__global__ __launch_bounds__(288, 3) void fused_kernel(
    const float* __restrict__ X, const float* __restrict__ W,
    const float* __restrict__ bias, float* __restrict__ out) {
  __shared__ __align__(16) float Ws[4 * WBUF];
  __shared__ __align__(16) float Xs[4 * XBUF];   // reused for sign bytes later
  __shared__ __align__(16) float sO2[NP * 120];  // 6 rows x stride 20 (16 data)
  __shared__ __align__(16) float sO1[NP * 48];   // 4 rows x 12 (base col 4tx-4)
  __shared__ __align__(16) float sO0[NP * 24];   // 3 rows x 8 (base a0x)

  const int tid = threadIdx.x;
  const int wrp = tid >> 5, ln = tid & 31;
  const int n = blockIdx.y;
  const int ty = blockIdx.x >> 4, tx = blockIdx.x & 15;
  const int y0 = ty << 3, x0 = tx << 4;

  // ---- mainloop slot addressing ----
  const bool hasx = tid < 256;
  const int ch_ = tid >> 5, t_ = tid & 31;
  const unsigned xd0 = su32(&Xs[ch_ * 128 + 4 * t_]);
  const float* Xn = X + (size_t)n * 64 * 65536;
  const float* xsrc = Xn + (size_t)ch_ * 65536 + (y0 + (t_ >> 2)) * 256 + x0 + ((t_ & 3) << 2);
  const int ka = tid / 66, pa = tid - 66 * ka;
  const int sb_ = tid + 288;
  const bool hasb = sb_ < 528;
  const int kb = sb_ / 66, pb = sb_ - 66 * kb;
  const unsigned wda0 = su32(&Ws[ka * NPP + pa]);
  const unsigned wdb0 = su32(&Ws[kb * NPP + pb]);
  const float* wsa = W + pa * 64 + ka;
  const float* wsb = W + pb * 64 + kb;

  ISSUE_CHUNK(0, 65536); CPA_COMMIT();
  ISSUE_CHUNK(1, 65536); CPA_COMMIT();
  ISSUE_CHUNK(2, 65536); CPA_COMMIT();

  // ---- sO staging (group 3) ----
  const int by2 = (y0 >> 1) - 1, a2 = 8 * tx - 4;
  const int by1 = (y0 >> 2) - 1, a1 = 4 * tx - 4;
  const int by0 = (y0 >> 3) - 1;
  const int bx0 = 2 * tx - 1, a0x = bx0 & ~3, off0 = bx0 & 3;
  const float* s2g = g_O2 + (size_t)n * NP * 16384;
  const float* s1g = g_O1 + (size_t)n * NP * 4096;
  const float* s0g = g_O0 + (size_t)n * NP * 1024;

  if (tx >= 1 && tx <= 14) {
    for (int i = tid; i < NP * 24; i += 288) {         // O2: 6 rows x 4 chunks
      int p = i / 24, r = i - p * 24;
      int rr = r >> 2, c4 = (r & 3) << 2;
      int sy = min(max(by2 + rr, 0), 127);
      cpa16(su32(&sO2[p * 120 + rr * 20 + c4]), s2g + p * 16384 + sy * 128 + a2 + c4);
    }
    for (int i = tid; i < NP * 12; i += 288) {         // O1: 4 rows x 3 chunks
      int p = i / 12, r = i - p * 12;
      int rr = r / 3, c4 = (r - rr * 3) << 2;
      int sy = min(max(by1 + rr, 0), 63);
      cpa16(su32(&sO1[p * 48 + rr * 12 + c4]), s1g + p * 4096 + sy * 64 + a1 + c4);
    }
    for (int i = tid; i < NP * 6; i += 288) {          // O0: 3 rows x 2 chunks
      int p = i / 6, r = i - p * 6;
      int rr = r >> 1, c4 = (r & 1) << 2;
      int sy = min(max(by0 + rr, 0), 31);
      cpa16(su32(&sO0[p * 24 + rr * 8 + c4]), s0g + p * 1024 + sy * 32 + a0x + c4);
    }
  } else {  // edge tiles: scalar clamped staging (same layouts)
    for (int i = tid; i < NP * 96; i += 288) {
      int p = i / 96, r = i - p * 96;
      int rr = r >> 4, c = r & 15;
      int sy = min(max(by2 + rr, 0), 127);
      int sx = min(max(a2 + c, 0), 127);
      cpa4(su32(&sO2[p * 120 + rr * 20 + c]), s2g + p * 16384 + sy * 128 + sx);
    }
    for (int i = tid; i < NP * 48; i += 288) {
      int p = i / 48, r = i - p * 48;
      int rr = r / 12, c = r - rr * 12;
      int sy = min(max(by1 + rr, 0), 63);
      int sx = min(max(a1 + c, 0), 63);
      cpa4(su32(&sO1[p * 48 + rr * 12 + c]), s1g + p * 4096 + sy * 64 + sx);
    }
    for (int i = tid; i < NP * 24; i += 288) {
      int p = i / 24, r = i - p * 24;
      int rr = r >> 3, c = r & 7;
      int sy = min(max(by0 + rr, 0), 31);
      int sx = min(max(a0x + c, 0), 31);
      cpa4(su32(&sO0[p * 24 + rr * 8 + c]), s0g + p * 1024 + sy * 32 + sx);
    }
  }
  CPA_COMMIT();   // group 3 = staging

  // zero the weight pad slots of all 4 buffers
  if (tid < 192) {
    int b = tid / 48, r = tid - 48 * b;
    int k = r / 6, p = 66 + (r - 6 * k);
    Ws[b * WBUF + k * NPP + p] = 0.0f;
  }

  // ---- stage3 GEMM mainloop (C=64), 4-deep cp.async ring ----
  unsigned long long acc[8][2];
#pragma unroll
  for (int a = 0; a < 8; a++) {
    int p = 8 * wrp + a;
    unsigned long long pk = pack2((p < NP) ? bias[p] : 0.0f);
    acc[a][0] = pk; acc[a][1] = pk;
  }

  for (int i = 0; i < 8; i++) {
    CPA_WAIT(2);
    __syncthreads();
    {
      const float* Wb = Ws + (i & 3) * WBUF;
      const float* Xb = Xs + (i & 3) * XBUF;
      COMPUTE8(Wb, Xb);
    }
    if (i + 3 < 8) ISSUE_CHUNK(i + 3, 65536);
    CPA_COMMIT();
  }
  __syncthreads();  // all compute done; Xs ring now dead -> reuse for signs

  // ---- epilogue: separable bilinear (quad-shared taps) + sign bytes ----
  {
    const int r = ln >> 2, qc = ln & 3;
    const int ry2 = c_RY[r];      const float wy2 = c_WY[r];
    const int ry1 = c_RY[8 + r];  const float wy1 = c_WY[8 + r];
    const int ry0 = c_RY[16 + r]; const float wy0 = c_WY[16 + r];
    const int w0qc = (qc + 1) >> 1;       // {0,1,1,2}
    const float fx0adj = (qc & 1) ? 0.5f : 0.0f;

    const int   LX2[4] = {0, 1, 1, 2};
    const float FX2[4] = {.75f, .25f, .75f, .25f};
    const int   LX1[4] = {0, 0, 1, 1};
    const float FX1[4] = {.625f, .875f, .125f, .375f};
    const float FX0[4] = {.5625f, .6875f, .8125f, .9375f};

    const int o2 = ry2 * 20 + 3 + 2 * qc;
    const int o1 = ry1 * 12 + 3 + qc;
    const int o0 = ry0 * 8 + off0 + w0qc;

    unsigned by[4] = {0, 0, 0, 0};
#pragma unroll
    for (int a = 0; a < 8; a++) {
      int p = 8 * wrp + a;
      float v[4];
      float2 u0 = unpack2(acc[a][0]), u1 = unpack2(acc[a][1]);
      v[0] = u0.x; v[1] = u0.y; v[2] = u1.x; v[3] = u1.y;
      if (p < NP) {
        const float* A2 = &sO2[p * 120 + o2];
        float t2[4];
#pragma unroll
        for (int t = 0; t < 4; t++) t2[t] = A2[t] + wy2 * (A2[t + 20] - A2[t]);
        const float* A1 = &sO1[p * 48 + o1];
        float t1[3];
#pragma unroll
        for (int t = 0; t < 3; t++) t1[t] = A1[t] + wy1 * (A1[t + 12] - A1[t]);
        const float* A0 = &sO0[p * 24 + o0];
        float t0a = A0[0] + wy0 * (A0[8] - A0[0]);
        float t0b = A0[1] + wy0 * (A0[9] - A0[1]);
#pragma unroll
        for (int q = 0; q < 4; q++) {
          v[q] += t2[LX2[q]] + FX2[q] * (t2[LX2[q] + 1] - t2[LX2[q]]);
          v[q] += t1[LX1[q]] + FX1[q] * (t1[LX1[q] + 1] - t1[LX1[q]]);
          float f0 = FX0[q] - fx0adj;
          v[q] += t0a + f0 * (t0b - t0a);
        }
      }
#pragma unroll
      for (int q = 0; q < 4; q++) by[q] |= ((v[q] > 0.0f) ? 1u : 0u) << a;
    }
    unsigned* sS32 = (unsigned*)Xs;
    sS32[wrp * 32 + ln] = by[0] | (by[1] << 8) | (by[2] << 16) | (by[3] << 24);
  }
  __syncthreads();

  // ---- vote via popcount against constant masks, coalesced store ----
  if (tid < 128) {
    const unsigned char* sb8 = (const unsigned char*)Xs;
    unsigned b0 = sb8[tid],           b1 = sb8[128 + tid];
    unsigned b2 = sb8[256 + tid],     b3 = sb8[384 + tid];
    unsigned b4 = sb8[512 + tid],     b5 = sb8[640 + tid];
    unsigned b6 = sb8[768 + tid],     b7 = sb8[896 + tid];
    unsigned b8 = sb8[1024 + tid];
    unsigned sw0 = b0 | (b1 << 8) | (b2 << 16) | (b3 << 24);
    unsigned sw1 = b4 | (b5 << 8) | (b6 << 16) | (b7 << 24);
    unsigned sw2 = b8;
    int row = tid >> 4, col = tid & 15;
    float* op = out + (size_t)n * 12 * 65536 + (y0 + row) * 256 + (x0 + col);
#pragma unroll
    for (int k = 0; k < 12; k++) {
      int4 A = c_MA[k];
      int4 B = c_MB[k];
      int cnt = __popc(sw0 & (unsigned)A.x) + __popc(sw1 & (unsigned)A.y) +
                __popc(sw2 & (unsigned)A.z) - __popc(sw0 & (unsigned)A.w) -
                __popc(sw1 & (unsigned)B.x) - __popc(sw2 & (unsigned)B.y) + k;
      op[(size_t)k << 16] = (float)cnt;
    }
  }
}

// ---------------- launcher ----------------
extern "C" void kernel_launch(void* const* d_in, const int* in_sizes, int n_in,
                              void* d_out, int out_size) {
  const float* st[4] = {0, 0, 0, 0};
  const float* w[4] = {0, 0, 0, 0};
  const float* bb[4] = {0, 0, 0, 0};
  int bc = 0;
  for (int i = 0; i < n_in; i++) {
    switch (in_sizes[i]) {
      case 4194304:  st[0] = (const float*)d_in[i]; break;  // 8*512*32*32
      case 8388608:  st[1] = (const float*)d_in[i]; break;  // 8*256*64*64
      case 16777216: st[2] = (const float*)d_in[i]; break;  // 8*128*128*128
      case 33554432: st[3] = (const float*)d_in[i]; break;  // 8*64*256*256
      case 33792: w[0] = (const float*)d_in[i]; break;      // 66*512
      case 16896: w[1] = (const float*)d_in[i]; break;      // 66*256
      case 8448:  w[2] = (const float*)d_in[i]; break;      // 66*128
      case 4224:  w[3] = (const float*)d_in[i]; break;      // 66*64
      case 66:
        if (bc < 4) bb[bc++] = (const float*)d_in[i];       // b0..b3 in order
        break;
      default: break;  // last_only (==1 always per setup_inputs)
    }
  }

  // prefer max shared carveout so 3 fused CTAs fit (idempotent, no alloc)
  cudaFuncSetAttribute(fused_kernel,
                       cudaFuncAttributePreferredSharedMemoryCarveout, 100);
  cudaFuncSetAttribute(conv_all,
                       cudaFuncAttributePreferredSharedMemoryCarveout, 100);

  conv_all<<<1344, 288>>>(st[0], st[1], st[2], w[0], w[1], w[2],
                          bb[0], bb[1], bb[2]);
  fused_kernel<<<dim3(512, 8), 288>>>(st[3], w[3], bb[3], (float*)d_out);
}